// round 2
// baseline (speedup 1.0000x reference)
#include <cuda_runtime.h>
#include <math.h>

#define B 8
#define NSEQ 512
#define IDX 256
#define HCTX 512
#define DF 768
#define PROJ 256
#define HID 128
#define NH 12
#define HD 64
#define VOCAB 16384
#define TOPK 20

// ---------------- scratch (static device globals; allocated at module load) --------------
__device__ float g_emb[B*NSEQ*DF];
__device__ float g_q  [B*IDX*DF];
__device__ float g_k  [B*NSEQ*DF];
__device__ float g_v  [B*NSEQ*DF];
__device__ float g_sc [B*NH*IDX*NSEQ];
__device__ float g_o  [B*IDX*DF];
__device__ float g_xp [B*NSEQ*PROJ];
__device__ float g_h1 [B*NSEQ*HID];
__device__ float g_h2 [B*NSEQ*HID];
__device__ float g_sig[B*NSEQ];
__device__ float g_e  [B*NSEQ*DF];
__device__ float g_sq [B*NSEQ];
__device__ float g_W  [B*NSEQ*NSEQ];
__device__ unsigned char g_mk[B*NSEQ*NSEQ];
__device__ int   g_ind[B*NSEQ*TOPK];
__device__ float g_dg [B*NSEQ];
__device__ float g_A  [B*NSEQ*NSEQ];
__device__ float g_T  [B*4*128*128];

// ---------------- block reduction helpers ----------------
__device__ __forceinline__ float blockReduceSum(float val, float* red) {
    int lane = threadIdx.x & 31, wid = threadIdx.x >> 5;
    #pragma unroll
    for (int off = 16; off; off >>= 1) val += __shfl_down_sync(0xffffffffu, val, off);
    if (lane == 0) red[wid] = val;
    __syncthreads();
    int nw = blockDim.x >> 5;
    val = (threadIdx.x < nw) ? red[threadIdx.x] : 0.f;
    if (wid == 0) {
        #pragma unroll
        for (int off = 16; off; off >>= 1) val += __shfl_down_sync(0xffffffffu, val, off);
        if (lane == 0) red[0] = val;
    }
    __syncthreads();
    float r = red[0];
    __syncthreads();
    return r;
}

__device__ __forceinline__ float blockReduceMax(float val, float* red) {
    int lane = threadIdx.x & 31, wid = threadIdx.x >> 5;
    #pragma unroll
    for (int off = 16; off; off >>= 1) val = fmaxf(val, __shfl_down_sync(0xffffffffu, val, off));
    if (lane == 0) red[wid] = val;
    __syncthreads();
    int nw = blockDim.x >> 5;
    val = (threadIdx.x < nw) ? red[threadIdx.x] : -3.4e38f;
    if (wid == 0) {
        #pragma unroll
        for (int off = 16; off; off >>= 1) val = fmaxf(val, __shfl_down_sync(0xffffffffu, val, off));
        if (lane == 0) red[0] = val;
    }
    __syncthreads();
    float r = red[0];
    __syncthreads();
    return r;
}

// ---------------- emb = concat(ge, ue) + PE ----------------
__global__ void build_emb(const float* __restrict__ ge, const float* __restrict__ ue,
                          float* __restrict__ emb) {
    long long idx = (long long)blockIdx.x * 256 + threadIdx.x;
    if (idx >= (long long)B*NSEQ*DF) return;
    int d = (int)(idx % DF);
    long long bn = idx / DF;
    int n = (int)(bn % NSEQ);
    int b = (int)(bn / NSEQ);
    float src = (n < IDX) ? ge[((long long)b*IDX + n)*DF + d]
                          : ue[((long long)b*IDX + (n - IDX))*DF + d];
    int i = d >> 1;
    float coef = (float)(-9.210340371976184 / 768.0);
    float div = expf((float)(2 * i) * coef);
    float ang = (float)n * div;
    float pe = (d & 1) ? cosf(ang) : sinf(ang);
    emb[idx] = src + pe;
}

// ---------------- generic tiled SGEMM: C = scale*(A@opB) + bias ----------------
// A row-major [M,K] (lda). TB: B row-major [N,K] (ldb), C += A@B^T.
// !TB: B row-major [K,N] (ldb), C += A@B. Batched: z -> (zb, zh).
template<bool TB>
__global__ void gemm(const float* __restrict__ A, const float* __restrict__ Bp,
                     float* __restrict__ C, const float* __restrict__ bias,
                     int M, int N, int K, int lda, int ldb, int ldc,
                     int ZH, long long Ab, long long Ah, long long Bb, long long Bh,
                     long long Cb, long long Ch, float scale) {
    __shared__ float As[16][65];
    __shared__ float Bs[16][65];
    int z = blockIdx.z;
    int zb = z / ZH, zh = z % ZH;
    A  += zb * Ab + zh * Ah;
    Bp += zb * Bb + zh * Bh;
    C  += zb * Cb + zh * Ch;
    int m0 = blockIdx.y * 64, n0 = blockIdx.x * 64;
    int tid = threadIdx.x;
    int tm = tid >> 4, tn = tid & 15;
    float acc[4][4] = {};
    for (int k0 = 0; k0 < K; k0 += 16) {
        #pragma unroll
        for (int r = 0; r < 4; r++) {
            int l = tid + r * 256;
            int m = l >> 4, kk = l & 15;
            float v = 0.f;
            if (m0 + m < M && k0 + kk < K) v = A[(long long)(m0 + m) * lda + k0 + kk];
            As[kk][m] = v;
        }
        #pragma unroll
        for (int r = 0; r < 4; r++) {
            int l = tid + r * 256;
            if (TB) {
                int n = l >> 4, kk = l & 15;
                float v = 0.f;
                if (n0 + n < N && k0 + kk < K) v = Bp[(long long)(n0 + n) * ldb + k0 + kk];
                Bs[kk][n] = v;
            } else {
                int kk = l >> 6, n = l & 63;
                float v = 0.f;
                if (k0 + kk < K && n0 + n < N) v = Bp[(long long)(k0 + kk) * ldb + n0 + n];
                Bs[kk][n] = v;
            }
        }
        __syncthreads();
        #pragma unroll
        for (int kk = 0; kk < 16; kk++) {
            float a[4], bv[4];
            #pragma unroll
            for (int u = 0; u < 4; u++) { a[u] = As[kk][tm * 4 + u]; bv[u] = Bs[kk][tn * 4 + u]; }
            #pragma unroll
            for (int u = 0; u < 4; u++)
                #pragma unroll
                for (int v2 = 0; v2 < 4; v2++) acc[u][v2] += a[u] * bv[v2];
        }
        __syncthreads();
    }
    #pragma unroll
    for (int u = 0; u < 4; u++) {
        int m = m0 + tm * 4 + u;
        if (m >= M) continue;
        #pragma unroll
        for (int v2 = 0; v2 < 4; v2++) {
            int n = n0 + tn * 4 + v2;
            if (n >= N) continue;
            float v = acc[u][v2] * scale;
            if (bias) v += bias[n];
            C[(long long)m * ldc + n] = v;
        }
    }
}

// ---------------- softmax over 512 (in place) ----------------
__global__ void softmax512(float* __restrict__ sc) {
    float* x = sc + (long long)blockIdx.x * NSEQ;
    __shared__ float red[32];
    int tid = threadIdx.x;
    float v0 = x[tid], v1 = x[tid + 256];
    float mx = blockReduceMax(fmaxf(v0, v1), red);
    float e0 = expf(v0 - mx), e1 = expf(v1 - mx);
    float s = blockReduceSum(e0 + e1, red);
    float inv = 1.f / s;
    x[tid] = e0 * inv;
    x[tid + 256] = e1 * inv;
}

// ---------------- u = LN(u + mha_out), written back into emb rows 256..511 ----------------
__global__ void ln_res(float* __restrict__ emb, const float* __restrict__ mo,
                       const float* __restrict__ g, const float* __restrict__ be) {
    int row = blockIdx.x;           // b*256 + i
    int b = row >> 8, i = row & 255;
    float* x = emb + ((long long)(b * NSEQ + IDX + i)) * DF;
    const float* y = mo + ((long long)(b * IDX + i)) * DF;
    __shared__ float red[32];
    int tid = threadIdx.x;
    float v[3]; float sum = 0.f;
    #pragma unroll
    for (int u = 0; u < 3; u++) { int d = tid + u * 256; v[u] = x[d] + y[d]; sum += v[u]; }
    sum = blockReduceSum(sum, red);
    float m = sum / 768.f;
    float vs = 0.f;
    #pragma unroll
    for (int u = 0; u < 3; u++) { float d = v[u] - m; vs += d * d; }
    vs = blockReduceSum(vs, red);
    float inv = 1.f / sqrtf(vs / 768.f + 1e-5f);
    #pragma unroll
    for (int u = 0; u < 3; u++) { int d = tid + u * 256; x[d] = (v[u] - m) * inv * g[d] + be[d]; }
}

// ---------------- conv1d(k=3,pad=1) + BN(eval) + ReLU, OC=128 ----------------
template<int IC>
__global__ void conv3bn(const float* __restrict__ x, const float* __restrict__ w,
                        const float* __restrict__ cb, const float* __restrict__ g,
                        const float* __restrict__ bb, float* __restrict__ y) {
    const int TC = 8;
    __shared__ float xs[(TC + 2) * IC];
    int b = blockIdx.y, t0 = blockIdx.x * TC, tid = threadIdx.x;
    for (int l = tid; l < (TC + 2) * IC; l += 128) {
        int r = l / IC, c = l - r * IC;
        int t = t0 - 1 + r;
        xs[l] = (t >= 0 && t < NSEQ) ? x[((long long)(b * NSEQ + t)) * IC + c] : 0.f;
    }
    __syncthreads();
    int o = tid;
    float acc[TC];
    #pragma unroll
    for (int u = 0; u < TC; u++) acc[u] = cb[o];
    const float* wo = w + (long long)o * IC * 3;
    for (int i = 0; i < IC; i++) {
        float w0 = wo[i * 3 + 0], w1 = wo[i * 3 + 1], w2 = wo[i * 3 + 2];
        #pragma unroll
        for (int u = 0; u < TC; u++)
            acc[u] += xs[u * IC + i] * w0 + xs[(u + 1) * IC + i] * w1 + xs[(u + 2) * IC + i] * w2;
    }
    const float inv = 0.9999950000375f;   // 1/sqrt(1+1e-5)
    float gg = g[o], bo = bb[o];
    #pragma unroll
    for (int u = 0; u < TC; u++) {
        float vv = acc[u] * inv * gg + bo;
        y[((long long)(b * NSEQ + t0 + u)) * HID + o] = fmaxf(vv, 0.f);
    }
}

// ---------------- sigma = h2 . ow + ob ----------------
__global__ void sigma_k(const float* __restrict__ h2, const float* __restrict__ ow,
                        const float* __restrict__ ob, float* __restrict__ sig) {
    int row = blockIdx.x;
    __shared__ float red[32];
    float v = h2[(long long)row * HID + threadIdx.x] * ow[threadIdx.x];
    v = blockReduceSum(v, red);
    if (threadIdx.x == 0) sig[row] = v + ob[0];
}

// ---------------- e = emb / (sigma+eps); sq = ||e||^2 ----------------
__global__ void e_sq(const float* __restrict__ emb, const float* __restrict__ sig,
                     float* __restrict__ e, float* __restrict__ sq) {
    int row = blockIdx.x;
    const float* x = emb + (long long)row * DF;
    float* y = e + (long long)row * DF;
    float s = sig[row] + 1e-6f;
    __shared__ float red[32];
    int tid = threadIdx.x;
    float acc = 0.f;
    #pragma unroll
    for (int u = 0; u < 3; u++) {
        int d = tid + u * 256;
        float v = x[d] / s;
        y[d] = v;
        acc += v * v;
    }
    acc = blockReduceSum(acc, red);
    if (tid == 0) sq[row] = acc;
}

// ---------------- W = exp(-(max(sq_r+sq_c-2G,0)/768)/2) ----------------
__global__ void wexp(float* __restrict__ W, const float* __restrict__ sq) {
    long long idx = (long long)blockIdx.x * 256 + threadIdx.x;
    if (idx >= (long long)B * NSEQ * NSEQ) return;
    int c = (int)(idx & 511);
    int r = (int)((idx >> 9) & 511);
    int b = (int)(idx >> 18);
    float d2 = sq[b * NSEQ + r] + sq[b * NSEQ + c] - 2.f * W[idx];
    d2 = fmaxf(d2, 0.f);
    W[idx] = expf(-(d2 / 768.f) * 0.5f);
}

// ---------------- top-20 per row (value desc, index asc tie-break) ----------------
__global__ void topk20(const float* __restrict__ W, int* __restrict__ ind) {
    int row = blockIdx.x;
    const float* x = W + (long long)row * NSEQ;
    int lane = threadIdx.x;
    float lv[16];
    #pragma unroll
    for (int j = 0; j < 16; j++) lv[j] = x[j * 32 + lane];
    for (int t = 0; t < TOPK; t++) {
        float bv = -2.f; int bi = 0;
        #pragma unroll
        for (int j = 0; j < 16; j++)
            if (lv[j] > bv) { bv = lv[j]; bi = j * 32 + lane; }
        #pragma unroll
        for (int off = 16; off; off >>= 1) {
            float ov = __shfl_down_sync(0xffffffffu, bv, off);
            int oi = __shfl_down_sync(0xffffffffu, bi, off);
            if (ov > bv || (ov == bv && oi < bi)) { bv = ov; bi = oi; }
        }
        bi = __shfl_sync(0xffffffffu, bi, 0);
        if (lane == 0) ind[row * TOPK + t] = bi;
        if (lane == (bi & 31)) {
            int js = bi >> 5;
            #pragma unroll
            for (int j = 0; j < 16; j++) if (j == js) lv[j] = -1.f;
        }
    }
}

// ---------------- symmetric mask scatter ----------------
__global__ void scat_mask(const int* __restrict__ ind, unsigned char* __restrict__ mk) {
    int row = blockIdx.x;             // b*512+n
    int b = row >> 9, n = row & 511;
    if (threadIdx.x < TOPK) {
        int m = ind[row * TOPK + threadIdx.x];
        mk[((long long)(b * NSEQ + n)) * NSEQ + m] = 1;
        mk[((long long)(b * NSEQ + m)) * NSEQ + n] = 1;
    }
}

// ---------------- W *= mask; Dg = rowsum ----------------
__global__ void maskW(float* __restrict__ W, const unsigned char* __restrict__ mk,
                      float* __restrict__ Dg) {
    int row = blockIdx.x;
    __shared__ float red[32];
    float sum = 0.f;
    for (int c = threadIdx.x; c < NSEQ; c += 256) {
        long long id = (long long)row * NSEQ + c;
        float w = mk[id] ? W[id] : 0.f;
        W[id] = w;
        sum += w;
    }
    sum = blockReduceSum(sum, red);
    if (threadIdx.x == 0) Dg[row] = sum;
}

// ---------------- A = (1+eps)I - alpha * D^-1/2 W D^-1/2 ----------------
__global__ void buildA(const float* __restrict__ W, const float* __restrict__ Dg,
                       const float* __restrict__ alpha, float* __restrict__ A) {
    long long idx = (long long)blockIdx.x * 256 + threadIdx.x;
    if (idx >= (long long)B * NSEQ * NSEQ) return;
    int c = (int)(idx & 511);
    int r = (int)((idx >> 9) & 511);
    int b = (int)(idx >> 18);
    float al = alpha[0];
    float dr = sqrtf(1.f / (Dg[b * NSEQ + r] + 1e-6f));
    float dc = sqrtf(1.f / (Dg[b * NSEQ + c] + 1e-6f));
    float s = dr * W[idx] * dc;
    A[idx] = ((r == c) ? (1.f + 1e-6f) : 0.f) - al * s;
}

// ---------------- blocked Gauss-Jordan inversion (4 blocks of 128, SPD, no pivot) -------
__global__ void gj_diag(float* __restrict__ Ag, int k) {
    extern __shared__ float s[];        // 128*128
    __shared__ float tcol[128];
    int b = blockIdx.x;
    float* Abase = Ag + (long long)b * NSEQ * NSEQ + (long long)(k * 128) * NSEQ + k * 128;
    int tid = threadIdx.x;              // 512
    for (int l = tid; l < 16384; l += 512) s[l] = Abase[(long long)(l >> 7) * NSEQ + (l & 127)];
    __syncthreads();
    for (int kk = 0; kk < 128; kk++) {
        float p = 1.0f / s[kk * 128 + kk];
        if (tid < 128) tcol[tid] = s[tid * 128 + kk];
        __syncthreads();
        if (tid < 128) s[kk * 128 + tid] = (tid == kk) ? p : s[kk * 128 + tid] * p;
        __syncthreads();
        int i = tid >> 2;
        int c0 = (tid & 3) * 32;
        if (i != kk) {
            float t = tcol[i];
            #pragma unroll 8
            for (int c = 0; c < 32; c++) {
                int j = c0 + c;
                if (j == kk) s[i * 128 + j] = -t * p;
                else         s[i * 128 + j] -= t * s[kk * 128 + j];
            }
        }
        __syncthreads();
    }
    for (int l = tid; l < 16384; l += 512) Abase[(long long)(l >> 7) * NSEQ + (l & 127)] = s[l];
}

__global__ void gj_panel(float* __restrict__ Ag, float* __restrict__ Tb, int k) {
    int b = blockIdx.y;
    int job = blockIdx.x;               // 0..5
    int jj = job % 3;
    int idx = jj + (jj >= k ? 1 : 0);
    float* Abase = Ag + (long long)b * NSEQ * NSEQ;
    if (job < 3) {
        const float* P = Abase + (long long)(k * 128) * NSEQ + k * 128;
        float* X = Abase + (long long)(k * 128) * NSEQ + idx * 128;
        __shared__ float As[16][132], Bs[16][132];
        int tid = threadIdx.x, tm = tid >> 4, tn = tid & 15;
        float acc[8][8] = {};
        for (int p0 = 0; p0 < 128; p0 += 16) {
            #pragma unroll
            for (int r = 0; r < 8; r++) { int l = tid + r * 256; int m = l >> 4, kk = l & 15;
                As[kk][m] = P[(long long)m * NSEQ + p0 + kk]; }
            #pragma unroll
            for (int r = 0; r < 8; r++) { int l = tid + r * 256; int kk = l >> 7, n = l & 127;
                Bs[kk][n] = X[(long long)(p0 + kk) * NSEQ + n]; }
            __syncthreads();
            #pragma unroll
            for (int kk = 0; kk < 16; kk++) {
                float a[8], bv[8];
                #pragma unroll
                for (int u = 0; u < 8; u++) { a[u] = As[kk][tm * 8 + u]; bv[u] = Bs[kk][tn * 8 + u]; }
                #pragma unroll
                for (int u = 0; u < 8; u++)
                    #pragma unroll
                    for (int v2 = 0; v2 < 8; v2++) acc[u][v2] += a[u] * bv[v2];
            }
            __syncthreads();
        }
        #pragma unroll
        for (int u = 0; u < 8; u++)
            #pragma unroll
            for (int v2 = 0; v2 < 8; v2++)
                X[(long long)(tm * 8 + u) * NSEQ + tn * 8 + v2] = acc[u][v2];
    } else {
        const float* S = Abase + (long long)(idx * 128) * NSEQ + k * 128;
        float* D = Tb + ((long long)b * 4 + idx) * 16384;
        for (int l = threadIdx.x; l < 16384; l += 256)
            D[l] = S[(long long)(l >> 7) * NSEQ + (l & 127)];
    }
}

__global__ void gj_update(float* __restrict__ Ag, const float* __restrict__ Tb, int k) {
    int b = blockIdx.y;
    int job = blockIdx.x;               // 0..11
    int ii = job >> 2;
    int i = ii + (ii >= k ? 1 : 0);
    int j = job & 3;
    float* Abase = Ag + (long long)b * NSEQ * NSEQ;
    const float* Tm = Tb + ((long long)b * 4 + i) * 16384;
    const float* Bm = Abase + (long long)(k * 128) * NSEQ + j * 128;
    float* Cm = Abase + (long long)(i * 128) * NSEQ + j * 128;
    __shared__ float As[16][132], Bs[16][132];
    int tid = threadIdx.x, tm = tid >> 4, tn = tid & 15;
    float acc[8][8] = {};
    for (int p0 = 0; p0 < 128; p0 += 16) {
        #pragma unroll
        for (int r = 0; r < 8; r++) { int l = tid + r * 256; int m = l >> 4, kk = l & 15;
            As[kk][m] = Tm[m * 128 + p0 + kk]; }
        #pragma unroll
        for (int r = 0; r < 8; r++) { int l = tid + r * 256; int kk = l >> 7, n = l & 127;
            Bs[kk][n] = Bm[(long long)(p0 + kk) * NSEQ + n]; }
        __syncthreads();
        #pragma unroll
        for (int kk = 0; kk < 16; kk++) {
            float a[8], bv[8];
            #pragma unroll
            for (int u = 0; u < 8; u++) { a[u] = As[kk][tm * 8 + u]; bv[u] = Bs[kk][tn * 8 + u]; }
            #pragma unroll
            for (int u = 0; u < 8; u++)
                #pragma unroll
                for (int v2 = 0; v2 < 8; v2++) acc[u][v2] += a[u] * bv[v2];
        }
        __syncthreads();
    }
    if (j != k) {
        #pragma unroll
        for (int u = 0; u < 8; u++)
            #pragma unroll
            for (int v2 = 0; v2 < 8; v2++) {
                long long id = (long long)(tm * 8 + u) * NSEQ + tn * 8 + v2;
                Cm[id] = Cm[id] - acc[u][v2];
            }
    } else {
        #pragma unroll
        for (int u = 0; u < 8; u++)
            #pragma unroll
            for (int v2 = 0; v2 < 8; v2++) {
                long long id = (long long)(tm * 8 + u) * NSEQ + tn * 8 + v2;
                Cm[id] = -acc[u][v2];
            }
    }
}

// ---------------- out[b,n,labels[b,m]] += prop[b,n,m] ----------------
__global__ void scat_out(const float* __restrict__ A, const int* __restrict__ labels,
                         float* __restrict__ out) {
    int m = blockIdx.x;
    int b = blockIdx.y;
    int v = labels[b * NSEQ + m];
    if (v < 0 || v >= VOCAB) return;
    const float* col = A + (long long)b * NSEQ * NSEQ + m;
    float* ob = out + (long long)b * NSEQ * VOCAB + v;
    for (int n = threadIdx.x; n < NSEQ; n += 256)
        atomicAdd(ob + (long long)n * VOCAB, col[(long long)n * NSEQ]);
}

// ==================================================================================
extern "C" void kernel_launch(void* const* d_in, const int* in_sizes, int n_in,
                              void* d_out, int out_size) {
    const float* ge     = (const float*)d_in[0];
    const float* ue     = (const float*)d_in[1];
    const float* hs     = (const float*)d_in[2];
    const int*   labels = (const int*)  d_in[3];
    const float* in_w   = (const float*)d_in[4];
    const float* in_b   = (const float*)d_in[5];
    const float* out_w  = (const float*)d_in[6];
    const float* out_b  = (const float*)d_in[7];
    const float* ln_g   = (const float*)d_in[8];
    const float* ln_b   = (const float*)d_in[9];
    const float* proj_w = (const float*)d_in[10];
    const float* proj_b = (const float*)d_in[11];
    const float* c1w    = (const float*)d_in[12];
    const float* c1b    = (const float*)d_in[13];
    const float* bn1g   = (const float*)d_in[14];
    const float* bn1b   = (const float*)d_in[15];
    const float* c2w    = (const float*)d_in[16];
    const float* c2b    = (const float*)d_in[17];
    const float* bn2g   = (const float*)d_in[18];
    const float* bn2b   = (const float*)d_in[19];
    const float* oww    = (const float*)d_in[20];
    const float* obb    = (const float*)d_in[21];
    const float* alpha  = (const float*)d_in[22];
    float* out = (float*)d_out;

    float *emb, *q, *k, *v, *sc, *o, *xp, *h1, *h2, *sig, *e, *sq, *W, *A, *T, *dg;
    unsigned char* mk; int* ind;
    cudaGetSymbolAddress((void**)&emb, g_emb);
    cudaGetSymbolAddress((void**)&q,   g_q);
    cudaGetSymbolAddress((void**)&k,   g_k);
    cudaGetSymbolAddress((void**)&v,   g_v);
    cudaGetSymbolAddress((void**)&sc,  g_sc);
    cudaGetSymbolAddress((void**)&o,   g_o);
    cudaGetSymbolAddress((void**)&xp,  g_xp);
    cudaGetSymbolAddress((void**)&h1,  g_h1);
    cudaGetSymbolAddress((void**)&h2,  g_h2);
    cudaGetSymbolAddress((void**)&sig, g_sig);
    cudaGetSymbolAddress((void**)&e,   g_e);
    cudaGetSymbolAddress((void**)&sq,  g_sq);
    cudaGetSymbolAddress((void**)&W,   g_W);
    cudaGetSymbolAddress((void**)&mk,  g_mk);
    cudaGetSymbolAddress((void**)&ind, g_ind);
    cudaGetSymbolAddress((void**)&dg,  g_dg);
    cudaGetSymbolAddress((void**)&A,   g_A);
    cudaGetSymbolAddress((void**)&T,   g_T);

    cudaFuncSetAttribute(gj_diag, cudaFuncAttributeMaxDynamicSharedMemorySize, 65536);

    // 1. embeddings + PE
    build_emb<<<(B*NSEQ*DF + 255) / 256, 256>>>(ge, ue, emb);

    // 2-4. QKV projections
    gemm<true><<<dim3(12, 4, B), 256>>>(emb + IDX*DF, in_w, q, in_b,
        IDX, DF, DF, DF, DF, DF, 1, (long long)NSEQ*DF, 0, 0, 0, (long long)IDX*DF, 0, 1.f);
    gemm<true><<<dim3(12, 8, B), 256>>>(hs, in_w + DF*DF, k, in_b + DF,
        NSEQ, DF, DF, DF, DF, DF, 1, (long long)NSEQ*DF, 0, 0, 0, (long long)NSEQ*DF, 0, 1.f);
    gemm<true><<<dim3(12, 8, B), 256>>>(hs, in_w + 2*DF*DF, v, in_b + 2*DF,
        NSEQ, DF, DF, DF, DF, DF, 1, (long long)NSEQ*DF, 0, 0, 0, (long long)NSEQ*DF, 0, 1.f);

    // 5. scores = QK^T / 8  (per b,h)
    gemm<true><<<dim3(8, 4, B*NH), 256>>>(q, k, sc, nullptr,
        IDX, NSEQ, HD, DF, DF, NSEQ, NH,
        (long long)IDX*DF, HD, (long long)NSEQ*DF, HD,
        (long long)NH*IDX*NSEQ, (long long)IDX*NSEQ, 0.125f);

    // 6. softmax
    softmax512<<<B*NH*IDX, 256>>>(sc);

    // 7. O = attn @ V
    gemm<false><<<dim3(1, 4, B*NH), 256>>>(sc, v, o, nullptr,
        IDX, HD, NSEQ, NSEQ, DF, DF, NH,
        (long long)NH*IDX*NSEQ, (long long)IDX*NSEQ, (long long)NSEQ*DF, HD,
        (long long)IDX*DF, HD, 1.f);

    // 8. out projection (reuse q as dest)
    gemm<true><<<dim3(12, 4, B), 256>>>(o, out_w, q, out_b,
        IDX, DF, DF, DF, DF, DF, 1, (long long)IDX*DF, 0, 0, 0, (long long)IDX*DF, 0, 1.f);

    // 9. residual + LN back into emb
    ln_res<<<B*IDX, 256>>>(emb, q, ln_g, ln_b);

    // 10. xp = emb @ proj_w^T + proj_b
    gemm<true><<<dim3(4, 8, B), 256>>>(emb, proj_w, xp, proj_b,
        NSEQ, PROJ, DF, DF, DF, PROJ, 1, (long long)NSEQ*DF, 0, 0, 0, (long long)NSEQ*PROJ, 0, 1.f);

    // 11-13. convs + sigma
    conv3bn<PROJ><<<dim3(64, B), 128>>>(xp, c1w, c1b, bn1g, bn1b, h1);
    conv3bn<HID ><<<dim3(64, B), 128>>>(h1, c2w, c2b, bn2g, bn2b, h2);
    sigma_k<<<B*NSEQ, 128>>>(h2, oww, obb, sig);

    // 14. e, sq
    e_sq<<<B*NSEQ, 256>>>(emb, sig, e, sq);

    // 15. Gram -> W buffer
    gemm<true><<<dim3(8, 8, B), 256>>>(e, e, W, nullptr,
        NSEQ, NSEQ, DF, DF, DF, NSEQ, 1,
        (long long)NSEQ*DF, 0, (long long)NSEQ*DF, 0, (long long)NSEQ*NSEQ, 0, 1.f);

    // 16. W = exp(-d2/1536)
    wexp<<<(B*NSEQ*NSEQ + 255) / 256, 256>>>(W, sq);

    // 17-20. topk, mask, Dg
    topk20<<<B*NSEQ, 32>>>(W, ind);
    cudaMemsetAsync(mk, 0, (size_t)B*NSEQ*NSEQ);
    scat_mask<<<B*NSEQ, 32>>>(ind, mk);
    maskW<<<B*NSEQ, 256>>>(W, mk, dg);

    // 21. A = (1+eps)I - alpha S
    buildA<<<(B*NSEQ*NSEQ + 255) / 256, 256>>>(W, dg, alpha, A);

    // 22-33. blocked Gauss-Jordan inverse (in place)
    for (int kb = 0; kb < 4; kb++) {
        gj_diag<<<B, 512, 65536>>>(A, kb);
        gj_panel<<<dim3(6, B), 256>>>(A, T, kb);
        gj_update<<<dim3(12, B), 256>>>(A, T, kb);
    }

    // 34-35. output = prop @ one_hot(labels)
    cudaMemsetAsync(out, 0, (size_t)out_size * sizeof(float));
    scat_out<<<dim3(NSEQ, B), 256>>>(A, labels, out);
}

// round 3
// speedup vs baseline: 1.0330x; 1.0330x over previous
#include <cuda_runtime.h>
#include <math.h>

#define B 8
#define NSEQ 512
#define IDX 256
#define HCTX 512
#define DF 768
#define PROJ 256
#define HID 128
#define NH 12
#define HD 64
#define VOCAB 16384
#define TOPK 20

// ---------------- scratch ----------------
__device__ float g_emb[B*NSEQ*DF];
__device__ float g_q  [B*IDX*DF];
__device__ float g_k  [B*NSEQ*DF];
__device__ float g_v  [B*NSEQ*DF];
__device__ float g_sc [B*NH*IDX*NSEQ];
__device__ float g_o  [B*IDX*DF];
__device__ float g_xp [B*NSEQ*PROJ];
__device__ float g_h1 [B*NSEQ*HID];
__device__ float g_h2 [B*NSEQ*HID];
__device__ float g_sig[B*NSEQ];
__device__ float g_e  [B*NSEQ*DF];
__device__ float g_sq [B*NSEQ];
__device__ float g_W  [B*NSEQ*NSEQ];
__device__ unsigned char g_mk[B*NSEQ*NSEQ];
__device__ int   g_ind[B*NSEQ*TOPK];
__device__ float g_dg [B*NSEQ];
__device__ float g_A  [B*NSEQ*NSEQ];
__device__ float g_T  [B*4*128*128];

// ---------------- reductions ----------------
__device__ __forceinline__ float blockReduceSum(float val, float* red) {
    int lane = threadIdx.x & 31, wid = threadIdx.x >> 5;
    #pragma unroll
    for (int off = 16; off; off >>= 1) val += __shfl_down_sync(0xffffffffu, val, off);
    if (lane == 0) red[wid] = val;
    __syncthreads();
    int nw = blockDim.x >> 5;
    val = (threadIdx.x < nw) ? red[threadIdx.x] : 0.f;
    if (wid == 0) {
        #pragma unroll
        for (int off = 16; off; off >>= 1) val += __shfl_down_sync(0xffffffffu, val, off);
        if (lane == 0) red[0] = val;
    }
    __syncthreads();
    float r = red[0];
    __syncthreads();
    return r;
}

__device__ __forceinline__ float blockReduceMax(float val, float* red) {
    int lane = threadIdx.x & 31, wid = threadIdx.x >> 5;
    #pragma unroll
    for (int off = 16; off; off >>= 1) val = fmaxf(val, __shfl_down_sync(0xffffffffu, val, off));
    if (lane == 0) red[wid] = val;
    __syncthreads();
    int nw = blockDim.x >> 5;
    val = (threadIdx.x < nw) ? red[threadIdx.x] : -3.4e38f;
    if (wid == 0) {
        #pragma unroll
        for (int off = 16; off; off >>= 1) val = fmaxf(val, __shfl_down_sync(0xffffffffu, val, off));
        if (lane == 0) red[0] = val;
    }
    __syncthreads();
    float r = red[0];
    __syncthreads();
    return r;
}

// ---------------- emb = concat(ge,ue) + PE ----------------
__global__ void build_emb(const float* __restrict__ ge, const float* __restrict__ ue,
                          float* __restrict__ emb) {
    long long idx = (long long)blockIdx.x * 256 + threadIdx.x;
    if (idx >= (long long)B*NSEQ*DF) return;
    int d = (int)(idx % DF);
    long long bn = idx / DF;
    int n = (int)(bn % NSEQ);
    int b = (int)(bn / NSEQ);
    float src = (n < IDX) ? ge[((long long)b*IDX + n)*DF + d]
                          : ue[((long long)b*IDX + (n - IDX))*DF + d];
    int i = d >> 1;
    float coef = (float)(-9.210340371976184 / 768.0);
    float div = expf((float)(2 * i) * coef);
    float ang = (float)n * div;
    float pe = (d & 1) ? cosf(ang) : sinf(ang);
    emb[idx] = src + pe;
}

// ==================================================================================
// Fast SGEMM: BM=128, BK=8, TM=8; BN/TN template (128/8 or 64/4); 256 threads.
// No bounds checks: requires M%128==0? No — M%128 handled by exact grid (all M are
// 256/512), N%BN==0, K%8==0, all pointers/ld 16B-aligned. Double-buffered smem.
// TB=true: B is [N,K] row-major (C = A@B^T). TB=false: B is [K,N].
// ==================================================================================
template<bool TB, int BN, int TN>
__global__ void __launch_bounds__(256) sgemm(
        const float* __restrict__ A, const float* __restrict__ Bp,
        float* __restrict__ C, const float* __restrict__ bias,
        int K, int lda, int ldb, int ldc,
        int ZH, long long Ab, long long Ah, long long Bb, long long Bh,
        long long Cb, long long Ch, float scale) {
    const int BM = 128, BK = 8, TM = 8;
    __shared__ float As[2][BK][BM + 4];
    __shared__ float Bs[2][BK][BN + 4];

    int z = blockIdx.z;
    int zb = z / ZH, zh = z - zb * ZH;
    A  += zb * Ab + zh * Ah;
    Bp += zb * Bb + zh * Bh;
    C  += zb * Cb + zh * Ch;
    int m0 = blockIdx.y * BM, n0 = blockIdx.x * BN;
    int tid = threadIdx.x;

    // A tile loader: 128 rows x 8 k -> 256 float4
    int a_row = tid >> 1;
    int a_kq  = (tid & 1) * 4;
    const float* Aptr = A + (long long)(m0 + a_row) * lda + a_kq;

    // B tile loader indices
    int b_row, b_kq, b_k, b_nq;
    const float* Bptr;
    if (TB) {
        if (BN == 128) { b_row = tid >> 1; b_kq = (tid & 1) * 4; }
        else           { b_row = tid >> 1; b_kq = (tid & 1) * 4; } // tid<128 active
        Bptr = Bp + (long long)(n0 + b_row) * ldb + b_kq;
        b_k = 0; b_nq = 0;
    } else {
        if (BN == 128) { b_k = tid >> 5; b_nq = (tid & 31) * 4; }
        else           { b_k = tid >> 4; b_nq = (tid & 15) * 4; } // tid<128 active
        Bptr = Bp + (long long)b_k * ldb + n0 + b_nq;
        b_row = 0; b_kq = 0;
    }
    const bool b_act = (BN == 128) || (tid < 128);

    int tn = tid & 15;          // 16 cols of threads
    int tm = tid >> 4;          // 16 rows of threads
    float acc[TM][TN];
    #pragma unroll
    for (int u = 0; u < TM; u++)
        #pragma unroll
        for (int v = 0; v < TN; v++) acc[u][v] = 0.f;

    int nt = K / BK;

    // --- load tile 0 ---
    {
        float4 ra = *(const float4*)Aptr;
        As[0][a_kq + 0][a_row] = ra.x;
        As[0][a_kq + 1][a_row] = ra.y;
        As[0][a_kq + 2][a_row] = ra.z;
        As[0][a_kq + 3][a_row] = ra.w;
        if (b_act) {
            float4 rb = *(const float4*)Bptr;
            if (TB) {
                Bs[0][b_kq + 0][b_row] = rb.x;
                Bs[0][b_kq + 1][b_row] = rb.y;
                Bs[0][b_kq + 2][b_row] = rb.z;
                Bs[0][b_kq + 3][b_row] = rb.w;
            } else {
                *(float4*)&Bs[0][b_k][b_nq] = rb;
            }
        }
    }
    __syncthreads();

    for (int t = 0; t < nt; t++) {
        int cur = t & 1;
        float4 ra, rb;
        bool pre = (t + 1 < nt);
        if (pre) {
            ra = *(const float4*)(Aptr + (long long)(t + 1) * BK);
            if (b_act) {
                if (TB) rb = *(const float4*)(Bptr + (long long)(t + 1) * BK);
                else    rb = *(const float4*)(Bptr + (long long)(t + 1) * BK * ldb);
            }
        }
        #pragma unroll
        for (int kk = 0; kk < BK; kk++) {
            float a[TM], bb[TN];
            #pragma unroll
            for (int u = 0; u < TM; u++) a[u] = As[cur][kk][tm * TM + u];
            #pragma unroll
            for (int v = 0; v < TN; v++) bb[v] = Bs[cur][kk][tn * TN + v];
            #pragma unroll
            for (int u = 0; u < TM; u++)
                #pragma unroll
                for (int v = 0; v < TN; v++) acc[u][v] += a[u] * bb[v];
        }
        if (pre) {
            int nxt = cur ^ 1;
            As[nxt][a_kq + 0][a_row] = ra.x;
            As[nxt][a_kq + 1][a_row] = ra.y;
            As[nxt][a_kq + 2][a_row] = ra.z;
            As[nxt][a_kq + 3][a_row] = ra.w;
            if (b_act) {
                if (TB) {
                    Bs[nxt][b_kq + 0][b_row] = rb.x;
                    Bs[nxt][b_kq + 1][b_row] = rb.y;
                    Bs[nxt][b_kq + 2][b_row] = rb.z;
                    Bs[nxt][b_kq + 3][b_row] = rb.w;
                } else {
                    *(float4*)&Bs[nxt][b_k][b_nq] = rb;
                }
            }
            __syncthreads();
        }
    }

    // --- epilogue ---
    #pragma unroll
    for (int u = 0; u < TM; u++) {
        int m = m0 + tm * TM + u;
        float* Crow = C + (long long)m * ldc + n0 + tn * TN;
        #pragma unroll
        for (int v = 0; v < TN; v += 4) {
            float4 o;
            o.x = acc[u][v + 0] * scale;
            o.y = acc[u][v + 1] * scale;
            o.z = acc[u][v + 2] * scale;
            o.w = acc[u][v + 3] * scale;
            if (bias) {
                const float* bp = bias + n0 + tn * TN + v;
                o.x += bp[0]; o.y += bp[1]; o.z += bp[2]; o.w += bp[3];
            }
            *(float4*)(Crow + v) = o;
        }
    }
}

// ---------------- softmax over 512 (in place) ----------------
__global__ void softmax512(float* __restrict__ sc) {
    float* x = sc + (long long)blockIdx.x * NSEQ;
    __shared__ float red[32];
    int tid = threadIdx.x;
    float v0 = x[tid], v1 = x[tid + 256];
    float mx = blockReduceMax(fmaxf(v0, v1), red);
    float e0 = expf(v0 - mx), e1 = expf(v1 - mx);
    float s = blockReduceSum(e0 + e1, red);
    float inv = 1.f / s;
    x[tid] = e0 * inv;
    x[tid + 256] = e1 * inv;
}

// ---------------- u = LN(u + mha_out) ----------------
__global__ void ln_res(float* __restrict__ emb, const float* __restrict__ mo,
                       const float* __restrict__ g, const float* __restrict__ be) {
    int row = blockIdx.x;
    int b = row >> 8, i = row & 255;
    float* x = emb + ((long long)(b * NSEQ + IDX + i)) * DF;
    const float* y = mo + ((long long)(b * IDX + i)) * DF;
    __shared__ float red[32];
    int tid = threadIdx.x;
    float v[3]; float sum = 0.f;
    #pragma unroll
    for (int u = 0; u < 3; u++) { int d = tid + u * 256; v[u] = x[d] + y[d]; sum += v[u]; }
    sum = blockReduceSum(sum, red);
    float m = sum / 768.f;
    float vs = 0.f;
    #pragma unroll
    for (int u = 0; u < 3; u++) { float d = v[u] - m; vs += d * d; }
    vs = blockReduceSum(vs, red);
    float inv = 1.f / sqrtf(vs / 768.f + 1e-5f);
    #pragma unroll
    for (int u = 0; u < 3; u++) { int d = tid + u * 256; x[d] = (v[u] - m) * inv * g[d] + be[d]; }
}

// ---------------- conv1d(k=3,pad=1)+BN+ReLU ----------------
template<int IC>
__global__ void conv3bn(const float* __restrict__ x, const float* __restrict__ w,
                        const float* __restrict__ cb, const float* __restrict__ g,
                        const float* __restrict__ bb, float* __restrict__ y) {
    const int TC = 8;
    __shared__ float xs[(TC + 2) * IC];
    int b = blockIdx.y, t0 = blockIdx.x * TC, tid = threadIdx.x;
    for (int l = tid; l < (TC + 2) * IC; l += 128) {
        int r = l / IC, c = l - r * IC;
        int t = t0 - 1 + r;
        xs[l] = (t >= 0 && t < NSEQ) ? x[((long long)(b * NSEQ + t)) * IC + c] : 0.f;
    }
    __syncthreads();
    int o = tid;
    float acc[TC];
    #pragma unroll
    for (int u = 0; u < TC; u++) acc[u] = cb[o];
    const float* wo = w + (long long)o * IC * 3;
    for (int i = 0; i < IC; i++) {
        float w0 = wo[i * 3 + 0], w1 = wo[i * 3 + 1], w2 = wo[i * 3 + 2];
        #pragma unroll
        for (int u = 0; u < TC; u++)
            acc[u] += xs[u * IC + i] * w0 + xs[(u + 1) * IC + i] * w1 + xs[(u + 2) * IC + i] * w2;
    }
    const float inv = 0.9999950000375f;
    float gg = g[o], bo = bb[o];
    #pragma unroll
    for (int u = 0; u < TC; u++) {
        float vv = acc[u] * inv * gg + bo;
        y[((long long)(b * NSEQ + t0 + u)) * HID + o] = fmaxf(vv, 0.f);
    }
}

// ---------------- sigma ----------------
__global__ void sigma_k(const float* __restrict__ h2, const float* __restrict__ ow,
                        const float* __restrict__ ob, float* __restrict__ sig) {
    int row = blockIdx.x;
    __shared__ float red[32];
    float v = h2[(long long)row * HID + threadIdx.x] * ow[threadIdx.x];
    v = blockReduceSum(v, red);
    if (threadIdx.x == 0) sig[row] = v + ob[0];
}

// ---------------- e, sq ----------------
__global__ void e_sq(const float* __restrict__ emb, const float* __restrict__ sig,
                     float* __restrict__ e, float* __restrict__ sq) {
    int row = blockIdx.x;
    const float* x = emb + (long long)row * DF;
    float* y = e + (long long)row * DF;
    float s = sig[row] + 1e-6f;
    __shared__ float red[32];
    int tid = threadIdx.x;
    float acc = 0.f;
    #pragma unroll
    for (int u = 0; u < 3; u++) {
        int d = tid + u * 256;
        float v = x[d] / s;
        y[d] = v;
        acc += v * v;
    }
    acc = blockReduceSum(acc, red);
    if (tid == 0) sq[row] = acc;
}

// ---------------- W = gaussian ----------------
__global__ void wexp(float* __restrict__ W, const float* __restrict__ sq) {
    long long idx = (long long)blockIdx.x * 256 + threadIdx.x;
    if (idx >= (long long)B * NSEQ * NSEQ) return;
    int c = (int)(idx & 511);
    int r = (int)((idx >> 9) & 511);
    int b = (int)(idx >> 18);
    float d2 = sq[b * NSEQ + r] + sq[b * NSEQ + c] - 2.f * W[idx];
    d2 = fmaxf(d2, 0.f);
    W[idx] = expf(-(d2 / 768.f) * 0.5f);
}

// ---------------- top-20 ----------------
__global__ void topk20(const float* __restrict__ W, int* __restrict__ ind) {
    int row = blockIdx.x;
    const float* x = W + (long long)row * NSEQ;
    int lane = threadIdx.x;
    float lv[16];
    #pragma unroll
    for (int j = 0; j < 16; j++) lv[j] = x[j * 32 + lane];
    for (int t = 0; t < TOPK; t++) {
        float bv = -2.f; int bi = 0;
        #pragma unroll
        for (int j = 0; j < 16; j++)
            if (lv[j] > bv) { bv = lv[j]; bi = j * 32 + lane; }
        #pragma unroll
        for (int off = 16; off; off >>= 1) {
            float ov = __shfl_down_sync(0xffffffffu, bv, off);
            int oi = __shfl_down_sync(0xffffffffu, bi, off);
            if (ov > bv || (ov == bv && oi < bi)) { bv = ov; bi = oi; }
        }
        bi = __shfl_sync(0xffffffffu, bi, 0);
        if (lane == 0) ind[row * TOPK + t] = bi;
        if (lane == (bi & 31)) {
            int js = bi >> 5;
            #pragma unroll
            for (int j = 0; j < 16; j++) if (j == js) lv[j] = -1.f;
        }
    }
}

// ---------------- mask scatter ----------------
__global__ void scat_mask(const int* __restrict__ ind, unsigned char* __restrict__ mk) {
    int row = blockIdx.x;
    int b = row >> 9, n = row & 511;
    if (threadIdx.x < TOPK) {
        int m = ind[row * TOPK + threadIdx.x];
        mk[((long long)(b * NSEQ + n)) * NSEQ + m] = 1;
        mk[((long long)(b * NSEQ + m)) * NSEQ + n] = 1;
    }
}

// ---------------- W*=mask, Dg ----------------
__global__ void maskW(float* __restrict__ W, const unsigned char* __restrict__ mk,
                      float* __restrict__ Dg) {
    int row = blockIdx.x;
    __shared__ float red[32];
    float sum = 0.f;
    for (int c = threadIdx.x; c < NSEQ; c += 256) {
        long long id = (long long)row * NSEQ + c;
        float w = mk[id] ? W[id] : 0.f;
        W[id] = w;
        sum += w;
    }
    sum = blockReduceSum(sum, red);
    if (threadIdx.x == 0) Dg[row] = sum;
}

// ---------------- A = (1+eps)I - alpha S ----------------
__global__ void buildA(const float* __restrict__ W, const float* __restrict__ Dg,
                       const float* __restrict__ alpha, float* __restrict__ A) {
    long long idx = (long long)blockIdx.x * 256 + threadIdx.x;
    if (idx >= (long long)B * NSEQ * NSEQ) return;
    int c = (int)(idx & 511);
    int r = (int)((idx >> 9) & 511);
    int b = (int)(idx >> 18);
    float al = alpha[0];
    float dr = sqrtf(1.f / (Dg[b * NSEQ + r] + 1e-6f));
    float dc = sqrtf(1.f / (Dg[b * NSEQ + c] + 1e-6f));
    float s = dr * W[idx] * dc;
    A[idx] = ((r == c) ? (1.f + 1e-6f) : 0.f) - al * s;
}

// ---------------- blocked Gauss-Jordan inversion ----------------
__global__ void gj_diag(float* __restrict__ Ag, int k) {
    extern __shared__ float s[];
    __shared__ float tcol[128];
    int b = blockIdx.x;
    float* Abase = Ag + (long long)b * NSEQ * NSEQ + (long long)(k * 128) * NSEQ + k * 128;
    int tid = threadIdx.x;
    for (int l = tid; l < 16384; l += 512) s[l] = Abase[(long long)(l >> 7) * NSEQ + (l & 127)];
    __syncthreads();
    for (int kk = 0; kk < 128; kk++) {
        float p = 1.0f / s[kk * 128 + kk];
        if (tid < 128) tcol[tid] = s[tid * 128 + kk];
        __syncthreads();
        if (tid < 128) s[kk * 128 + tid] = (tid == kk) ? p : s[kk * 128 + tid] * p;
        __syncthreads();
        int i = tid >> 2;
        int c0 = (tid & 3) * 32;
        if (i != kk) {
            float t = tcol[i];
            #pragma unroll 8
            for (int c = 0; c < 32; c++) {
                int j = c0 + c;
                if (j == kk) s[i * 128 + j] = -t * p;
                else         s[i * 128 + j] -= t * s[kk * 128 + j];
            }
        }
        __syncthreads();
    }
    for (int l = tid; l < 16384; l += 512) Abase[(long long)(l >> 7) * NSEQ + (l & 127)] = s[l];
}

__global__ void gj_panel(float* __restrict__ Ag, float* __restrict__ Tb, int k) {
    int b = blockIdx.y;
    int job = blockIdx.x;
    int jj = job % 3;
    int idx = jj + (jj >= k ? 1 : 0);
    float* Abase = Ag + (long long)b * NSEQ * NSEQ;
    if (job < 3) {
        const float* P = Abase + (long long)(k * 128) * NSEQ + k * 128;
        float* X = Abase + (long long)(k * 128) * NSEQ + idx * 128;
        __shared__ float As[16][132], Bs[16][132];
        int tid = threadIdx.x, tm = tid >> 4, tn = tid & 15;
        float acc[8][8] = {};
        for (int p0 = 0; p0 < 128; p0 += 16) {
            #pragma unroll
            for (int r = 0; r < 8; r++) { int l = tid + r * 256; int m = l >> 4, kk = l & 15;
                As[kk][m] = P[(long long)m * NSEQ + p0 + kk]; }
            #pragma unroll
            for (int r = 0; r < 8; r++) { int l = tid + r * 256; int kk = l >> 7, n = l & 127;
                Bs[kk][n] = X[(long long)(p0 + kk) * NSEQ + n]; }
            __syncthreads();
            #pragma unroll
            for (int kk = 0; kk < 16; kk++) {
                float a[8], bv[8];
                #pragma unroll
                for (int u = 0; u < 8; u++) { a[u] = As[kk][tm * 8 + u]; bv[u] = Bs[kk][tn * 8 + u]; }
                #pragma unroll
                for (int u = 0; u < 8; u++)
                    #pragma unroll
                    for (int v2 = 0; v2 < 8; v2++) acc[u][v2] += a[u] * bv[v2];
            }
            __syncthreads();
        }
        #pragma unroll
        for (int u = 0; u < 8; u++)
            #pragma unroll
            for (int v2 = 0; v2 < 8; v2++)
                X[(long long)(tm * 8 + u) * NSEQ + tn * 8 + v2] = acc[u][v2];
    } else {
        const float* S = Abase + (long long)(idx * 128) * NSEQ + k * 128;
        float* D = Tb + ((long long)b * 4 + idx) * 16384;
        for (int l = threadIdx.x; l < 16384; l += 256)
            D[l] = S[(long long)(l >> 7) * NSEQ + (l & 127)];
    }
}

__global__ void gj_update(float* __restrict__ Ag, const float* __restrict__ Tb, int k) {
    int b = blockIdx.y;
    int job = blockIdx.x;
    int ii = job >> 2;
    int i = ii + (ii >= k ? 1 : 0);
    int j = job & 3;
    float* Abase = Ag + (long long)b * NSEQ * NSEQ;
    const float* Tm = Tb + ((long long)b * 4 + i) * 16384;
    const float* Bm = Abase + (long long)(k * 128) * NSEQ + j * 128;
    float* Cm = Abase + (long long)(i * 128) * NSEQ + j * 128;
    __shared__ float As[16][132], Bs[16][132];
    int tid = threadIdx.x, tm = tid >> 4, tn = tid & 15;
    float acc[8][8] = {};
    for (int p0 = 0; p0 < 128; p0 += 16) {
        #pragma unroll
        for (int r = 0; r < 8; r++) { int l = tid + r * 256; int m = l >> 4, kk = l & 15;
            As[kk][m] = Tm[m * 128 + p0 + kk]; }
        #pragma unroll
        for (int r = 0; r < 8; r++) { int l = tid + r * 256; int kk = l >> 7, n = l & 127;
            Bs[kk][n] = Bm[(long long)(p0 + kk) * NSEQ + n]; }
        __syncthreads();
        #pragma unroll
        for (int kk = 0; kk < 16; kk++) {
            float a[8], bv[8];
            #pragma unroll
            for (int u = 0; u < 8; u++) { a[u] = As[kk][tm * 8 + u]; bv[u] = Bs[kk][tn * 8 + u]; }
            #pragma unroll
            for (int u = 0; u < 8; u++)
                #pragma unroll
                for (int v2 = 0; v2 < 8; v2++) acc[u][v2] += a[u] * bv[v2];
        }
        __syncthreads();
    }
    if (j != k) {
        #pragma unroll
        for (int u = 0; u < 8; u++)
            #pragma unroll
            for (int v2 = 0; v2 < 8; v2++) {
                long long id = (long long)(tm * 8 + u) * NSEQ + tn * 8 + v2;
                Cm[id] = Cm[id] - acc[u][v2];
            }
    } else {
        #pragma unroll
        for (int u = 0; u < 8; u++)
            #pragma unroll
            for (int v2 = 0; v2 < 8; v2++) {
                long long id = (long long)(tm * 8 + u) * NSEQ + tn * 8 + v2;
                Cm[id] = -acc[u][v2];
            }
    }
}

// ---------------- output scatter ----------------
__global__ void scat_out(const float* __restrict__ A, const int* __restrict__ labels,
                         float* __restrict__ out) {
    int m = blockIdx.x;
    int b = blockIdx.y;
    int v = labels[b * NSEQ + m];
    if (v < 0 || v >= VOCAB) return;
    const float* col = A + (long long)b * NSEQ * NSEQ + m;
    float* ob = out + (long long)b * NSEQ * VOCAB + v;
    for (int n = threadIdx.x; n < NSEQ; n += 256)
        atomicAdd(ob + (long long)n * VOCAB, col[(long long)n * NSEQ]);
}

// ==================================================================================
extern "C" void kernel_launch(void* const* d_in, const int* in_sizes, int n_in,
                              void* d_out, int out_size) {
    const float* ge     = (const float*)d_in[0];
    const float* ue     = (const float*)d_in[1];
    const float* hs     = (const float*)d_in[2];
    const int*   labels = (const int*)  d_in[3];
    const float* in_w   = (const float*)d_in[4];
    const float* in_b   = (const float*)d_in[5];
    const float* out_w  = (const float*)d_in[6];
    const float* out_b  = (const float*)d_in[7];
    const float* ln_g   = (const float*)d_in[8];
    const float* ln_b   = (const float*)d_in[9];
    const float* proj_w = (const float*)d_in[10];
    const float* proj_b = (const float*)d_in[11];
    const float* c1w    = (const float*)d_in[12];
    const float* c1b    = (const float*)d_in[13];
    const float* bn1g   = (const float*)d_in[14];
    const float* bn1b   = (const float*)d_in[15];
    const float* c2w    = (const float*)d_in[16];
    const float* c2b    = (const float*)d_in[17];
    const float* bn2g   = (const float*)d_in[18];
    const float* bn2b   = (const float*)d_in[19];
    const float* oww    = (const float*)d_in[20];
    const float* obb    = (const float*)d_in[21];
    const float* alpha  = (const float*)d_in[22];
    float* out = (float*)d_out;

    float *emb, *q, *k, *v, *sc, *o, *xp, *h1, *h2, *sig, *e, *sq, *W, *A, *T, *dg;
    unsigned char* mk; int* ind;
    cudaGetSymbolAddress((void**)&emb, g_emb);
    cudaGetSymbolAddress((void**)&q,   g_q);
    cudaGetSymbolAddress((void**)&k,   g_k);
    cudaGetSymbolAddress((void**)&v,   g_v);
    cudaGetSymbolAddress((void**)&sc,  g_sc);
    cudaGetSymbolAddress((void**)&o,   g_o);
    cudaGetSymbolAddress((void**)&xp,  g_xp);
    cudaGetSymbolAddress((void**)&h1,  g_h1);
    cudaGetSymbolAddress((void**)&h2,  g_h2);
    cudaGetSymbolAddress((void**)&sig, g_sig);
    cudaGetSymbolAddress((void**)&e,   g_e);
    cudaGetSymbolAddress((void**)&sq,  g_sq);
    cudaGetSymbolAddress((void**)&W,   g_W);
    cudaGetSymbolAddress((void**)&mk,  g_mk);
    cudaGetSymbolAddress((void**)&ind, g_ind);
    cudaGetSymbolAddress((void**)&dg,  g_dg);
    cudaGetSymbolAddress((void**)&A,   g_A);
    cudaGetSymbolAddress((void**)&T,   g_T);

    cudaFuncSetAttribute(gj_diag, cudaFuncAttributeMaxDynamicSharedMemorySize, 65536);

    // 1. embeddings + PE
    build_emb<<<(B*NSEQ*DF + 255) / 256, 256>>>(ge, ue, emb);

    // 2-4. QKV projections (C = X @ W^T + b)
    sgemm<true,128,8><<<dim3(6, 2, B), 256>>>(emb + IDX*DF, in_w, q, in_b,
        DF, DF, DF, DF, 1, (long long)NSEQ*DF, 0, 0, 0, (long long)IDX*DF, 0, 1.f);
    sgemm<true,128,8><<<dim3(6, 4, B), 256>>>(hs, in_w + DF*DF, k, in_b + DF,
        DF, DF, DF, DF, 1, (long long)NSEQ*DF, 0, 0, 0, (long long)NSEQ*DF, 0, 1.f);
    sgemm<true,128,8><<<dim3(6, 4, B), 256>>>(hs, in_w + 2*DF*DF, v, in_b + 2*DF,
        DF, DF, DF, DF, 1, (long long)NSEQ*DF, 0, 0, 0, (long long)NSEQ*DF, 0, 1.f);

    // 5. scores = QK^T / 8
    sgemm<true,128,8><<<dim3(4, 2, B*NH), 256>>>(q, k, sc, nullptr,
        HD, DF, DF, NSEQ, NH,
        (long long)IDX*DF, HD, (long long)NSEQ*DF, HD,
        (long long)NH*IDX*NSEQ, (long long)IDX*NSEQ, 0.125f);

    // 6. softmax
    softmax512<<<B*NH*IDX, 256>>>(sc);

    // 7. O = attn @ V  (B not transposed, N=64)
    sgemm<false,64,4><<<dim3(1, 2, B*NH), 256>>>(sc, v, o, nullptr,
        NSEQ, NSEQ, DF, DF, NH,
        (long long)NH*IDX*NSEQ, (long long)IDX*NSEQ, (long long)NSEQ*DF, HD,
        (long long)IDX*DF, HD, 1.f);

    // 8. out projection (dest q)
    sgemm<true,128,8><<<dim3(6, 2, B), 256>>>(o, out_w, q, out_b,
        DF, DF, DF, DF, 1, (long long)IDX*DF, 0, 0, 0, (long long)IDX*DF, 0, 1.f);

    // 9. residual + LN
    ln_res<<<B*IDX, 256>>>(emb, q, ln_g, ln_b);

    // 10. xp = emb @ proj_w^T + proj_b
    sgemm<true,128,8><<<dim3(2, 4, B), 256>>>(emb, proj_w, xp, proj_b,
        DF, DF, DF, PROJ, 1, (long long)NSEQ*DF, 0, 0, 0, (long long)NSEQ*PROJ, 0, 1.f);

    // 11-13. convs + sigma
    conv3bn<PROJ><<<dim3(64, B), 128>>>(xp, c1w, c1b, bn1g, bn1b, h1);
    conv3bn<HID ><<<dim3(64, B), 128>>>(h1, c2w, c2b, bn2g, bn2b, h2);
    sigma_k<<<B*NSEQ, 128>>>(h2, oww, obb, sig);

    // 14. e, sq
    e_sq<<<B*NSEQ, 256>>>(emb, sig, e, sq);

    // 15. Gram
    sgemm<true,128,8><<<dim3(4, 4, B), 256>>>(e, e, W, nullptr,
        DF, DF, DF, NSEQ, 1,
        (long long)NSEQ*DF, 0, (long long)NSEQ*DF, 0, (long long)NSEQ*NSEQ, 0, 1.f);

    // 16. W = exp(-d2/1536)
    wexp<<<(B*NSEQ*NSEQ + 255) / 256, 256>>>(W, sq);

    // 17-20. topk, mask, Dg
    topk20<<<B*NSEQ, 32>>>(W, ind);
    cudaMemsetAsync(mk, 0, (size_t)B*NSEQ*NSEQ);
    scat_mask<<<B*NSEQ, 32>>>(ind, mk);
    maskW<<<B*NSEQ, 256>>>(W, mk, dg);

    // 21. A
    buildA<<<(B*NSEQ*NSEQ + 255) / 256, 256>>>(W, dg, alpha, A);

    // 22-33. blocked GJ inverse
    for (int kb = 0; kb < 4; kb++) {
        gj_diag<<<B, 512, 65536>>>(A, kb);
        gj_panel<<<dim3(6, B), 256>>>(A, T, kb);
        gj_update<<<dim3(12, B), 256>>>(A, T, kb);
    }

    // 34-35. output scatter
    cudaMemsetAsync(out, 0, (size_t)out_size * sizeof(float));
    scat_out<<<dim3(NSEQ, B), 256>>>(A, labels, out);
}

// round 4
// speedup vs baseline: 1.0331x; 1.0001x over previous
#include <cuda_runtime.h>
#include <math.h>

#define B 8
#define NSEQ 512
#define IDX 256
#define HCTX 512
#define DF 768
#define PROJ 256
#define HID 128
#define NH 12
#define HD 64
#define VOCAB 16384
#define TOPK 20

// ---------------- scratch ----------------
__device__ float g_emb[B*NSEQ*DF];
__device__ float g_q  [B*IDX*DF];
__device__ float g_k  [B*NSEQ*DF];
__device__ float g_v  [B*NSEQ*DF];
__device__ float g_sc [B*NH*IDX*NSEQ];
__device__ float g_o  [B*IDX*DF];
__device__ float g_xp [B*NSEQ*PROJ];
__device__ float g_h1 [B*NSEQ*HID];
__device__ float g_h2 [B*NSEQ*HID];
__device__ float g_sig[B*NSEQ];
__device__ float g_e  [B*NSEQ*DF];
__device__ float g_sq [B*NSEQ];
__device__ float g_W  [B*NSEQ*NSEQ];
__device__ unsigned char g_mk[B*NSEQ*NSEQ];
__device__ int   g_ind[B*NSEQ*TOPK];
__device__ float g_dg [B*NSEQ];
__device__ float g_A  [B*NSEQ*NSEQ];
__device__ float g_T  [B*4*128*128];

// ---------------- reductions ----------------
__device__ __forceinline__ float blockReduceSum(float val, float* red) {
    int lane = threadIdx.x & 31, wid = threadIdx.x >> 5;
    #pragma unroll
    for (int off = 16; off; off >>= 1) val += __shfl_down_sync(0xffffffffu, val, off);
    if (lane == 0) red[wid] = val;
    __syncthreads();
    int nw = blockDim.x >> 5;
    val = (threadIdx.x < nw) ? red[threadIdx.x] : 0.f;
    if (wid == 0) {
        #pragma unroll
        for (int off = 16; off; off >>= 1) val += __shfl_down_sync(0xffffffffu, val, off);
        if (lane == 0) red[0] = val;
    }
    __syncthreads();
    float r = red[0];
    __syncthreads();
    return r;
}

__device__ __forceinline__ float blockReduceMax(float val, float* red) {
    int lane = threadIdx.x & 31, wid = threadIdx.x >> 5;
    #pragma unroll
    for (int off = 16; off; off >>= 1) val = fmaxf(val, __shfl_down_sync(0xffffffffu, val, off));
    if (lane == 0) red[wid] = val;
    __syncthreads();
    int nw = blockDim.x >> 5;
    val = (threadIdx.x < nw) ? red[threadIdx.x] : -3.4e38f;
    if (wid == 0) {
        #pragma unroll
        for (int off = 16; off; off >>= 1) val = fmaxf(val, __shfl_down_sync(0xffffffffu, val, off));
        if (lane == 0) red[0] = val;
    }
    __syncthreads();
    float r = red[0];
    __syncthreads();
    return r;
}

// ---------------- emb = concat(ge,ue) + PE ----------------
__global__ void build_emb(const float* __restrict__ ge, const float* __restrict__ ue,
                          float* __restrict__ emb) {
    long long idx = (long long)blockIdx.x * 256 + threadIdx.x;
    if (idx >= (long long)B*NSEQ*DF) return;
    int d = (int)(idx % DF);
    long long bn = idx / DF;
    int n = (int)(bn % NSEQ);
    int b = (int)(bn / NSEQ);
    float src = (n < IDX) ? ge[((long long)b*IDX + n)*DF + d]
                          : ue[((long long)b*IDX + (n - IDX))*DF + d];
    int i = d >> 1;
    float coef = (float)(-9.210340371976184 / 768.0);
    float div = expf((float)(2 * i) * coef);
    float ang = (float)n * div;
    float pe = (d & 1) ? cosf(ang) : sinf(ang);
    emb[idx] = src + pe;
}

// ==================================================================================
// Fast SGEMM: BM=128, BK=8, TM=8; BN/TN template (128/8 or 64/4); 256 threads.
// No bounds checks: requires M%128==0? No — M%128 handled by exact grid (all M are
// 256/512), N%BN==0, K%8==0, all pointers/ld 16B-aligned. Double-buffered smem.
// TB=true: B is [N,K] row-major (C = A@B^T). TB=false: B is [K,N].
// ==================================================================================
template<bool TB, int BN, int TN>
__global__ void __launch_bounds__(256) sgemm(
        const float* __restrict__ A, const float* __restrict__ Bp,
        float* __restrict__ C, const float* __restrict__ bias,
        int K, int lda, int ldb, int ldc,
        int ZH, long long Ab, long long Ah, long long Bb, long long Bh,
        long long Cb, long long Ch, float scale) {
    const int BM = 128, BK = 8, TM = 8;
    __shared__ float As[2][BK][BM + 4];
    __shared__ float Bs[2][BK][BN + 4];

    int z = blockIdx.z;
    int zb = z / ZH, zh = z - zb * ZH;
    A  += zb * Ab + zh * Ah;
    Bp += zb * Bb + zh * Bh;
    C  += zb * Cb + zh * Ch;
    int m0 = blockIdx.y * BM, n0 = blockIdx.x * BN;
    int tid = threadIdx.x;

    // A tile loader: 128 rows x 8 k -> 256 float4
    int a_row = tid >> 1;
    int a_kq  = (tid & 1) * 4;
    const float* Aptr = A + (long long)(m0 + a_row) * lda + a_kq;

    // B tile loader indices
    int b_row, b_kq, b_k, b_nq;
    const float* Bptr;
    if (TB) {
        if (BN == 128) { b_row = tid >> 1; b_kq = (tid & 1) * 4; }
        else           { b_row = tid >> 1; b_kq = (tid & 1) * 4; } // tid<128 active
        Bptr = Bp + (long long)(n0 + b_row) * ldb + b_kq;
        b_k = 0; b_nq = 0;
    } else {
        if (BN == 128) { b_k = tid >> 5; b_nq = (tid & 31) * 4; }
        else           { b_k = tid >> 4; b_nq = (tid & 15) * 4; } // tid<128 active
        Bptr = Bp + (long long)b_k * ldb + n0 + b_nq;
        b_row = 0; b_kq = 0;
    }
    const bool b_act = (BN == 128) || (tid < 128);

    int tn = tid & 15;          // 16 cols of threads
    int tm = tid >> 4;          // 16 rows of threads
    float acc[TM][TN];
    #pragma unroll
    for (int u = 0; u < TM; u++)
        #pragma unroll
        for (int v = 0; v < TN; v++) acc[u][v] = 0.f;

    int nt = K / BK;

    // --- load tile 0 ---
    {
        float4 ra = *(const float4*)Aptr;
        As[0][a_kq + 0][a_row] = ra.x;
        As[0][a_kq + 1][a_row] = ra.y;
        As[0][a_kq + 2][a_row] = ra.z;
        As[0][a_kq + 3][a_row] = ra.w;
        if (b_act) {
            float4 rb = *(const float4*)Bptr;
            if (TB) {
                Bs[0][b_kq + 0][b_row] = rb.x;
                Bs[0][b_kq + 1][b_row] = rb.y;
                Bs[0][b_kq + 2][b_row] = rb.z;
                Bs[0][b_kq + 3][b_row] = rb.w;
            } else {
                *(float4*)&Bs[0][b_k][b_nq] = rb;
            }
        }
    }
    __syncthreads();

    for (int t = 0; t < nt; t++) {
        int cur = t & 1;
        float4 ra, rb;
        bool pre = (t + 1 < nt);
        if (pre) {
            ra = *(const float4*)(Aptr + (long long)(t + 1) * BK);
            if (b_act) {
                if (TB) rb = *(const float4*)(Bptr + (long long)(t + 1) * BK);
                else    rb = *(const float4*)(Bptr + (long long)(t + 1) * BK * ldb);
            }
        }
        #pragma unroll
        for (int kk = 0; kk < BK; kk++) {
            float a[TM], bb[TN];
            #pragma unroll
            for (int u = 0; u < TM; u++) a[u] = As[cur][kk][tm * TM + u];
            #pragma unroll
            for (int v = 0; v < TN; v++) bb[v] = Bs[cur][kk][tn * TN + v];
            #pragma unroll
            for (int u = 0; u < TM; u++)
                #pragma unroll
                for (int v = 0; v < TN; v++) acc[u][v] += a[u] * bb[v];
        }
        if (pre) {
            int nxt = cur ^ 1;
            As[nxt][a_kq + 0][a_row] = ra.x;
            As[nxt][a_kq + 1][a_row] = ra.y;
            As[nxt][a_kq + 2][a_row] = ra.z;
            As[nxt][a_kq + 3][a_row] = ra.w;
            if (b_act) {
                if (TB) {
                    Bs[nxt][b_kq + 0][b_row] = rb.x;
                    Bs[nxt][b_kq + 1][b_row] = rb.y;
                    Bs[nxt][b_kq + 2][b_row] = rb.z;
                    Bs[nxt][b_kq + 3][b_row] = rb.w;
                } else {
                    *(float4*)&Bs[nxt][b_k][b_nq] = rb;
                }
            }
            __syncthreads();
        }
    }

    // --- epilogue ---
    #pragma unroll
    for (int u = 0; u < TM; u++) {
        int m = m0 + tm * TM + u;
        float* Crow = C + (long long)m * ldc + n0 + tn * TN;
        #pragma unroll
        for (int v = 0; v < TN; v += 4) {
            float4 o;
            o.x = acc[u][v + 0] * scale;
            o.y = acc[u][v + 1] * scale;
            o.z = acc[u][v + 2] * scale;
            o.w = acc[u][v + 3] * scale;
            if (bias) {
                const float* bp = bias + n0 + tn * TN + v;
                o.x += bp[0]; o.y += bp[1]; o.z += bp[2]; o.w += bp[3];
            }
            *(float4*)(Crow + v) = o;
        }
    }
}

// ---------------- softmax over 512 (in place) ----------------
__global__ void softmax512(float* __restrict__ sc) {
    float* x = sc + (long long)blockIdx.x * NSEQ;
    __shared__ float red[32];
    int tid = threadIdx.x;
    float v0 = x[tid], v1 = x[tid + 256];
    float mx = blockReduceMax(fmaxf(v0, v1), red);
    float e0 = expf(v0 - mx), e1 = expf(v1 - mx);
    float s = blockReduceSum(e0 + e1, red);
    float inv = 1.f / s;
    x[tid] = e0 * inv;
    x[tid + 256] = e1 * inv;
}

// ---------------- u = LN(u + mha_out) ----------------
__global__ void ln_res(float* __restrict__ emb, const float* __restrict__ mo,
                       const float* __restrict__ g, const float* __restrict__ be) {
    int row = blockIdx.x;
    int b = row >> 8, i = row & 255;
    float* x = emb + ((long long)(b * NSEQ + IDX + i)) * DF;
    const float* y = mo + ((long long)(b * IDX + i)) * DF;
    __shared__ float red[32];
    int tid = threadIdx.x;
    float v[3]; float sum = 0.f;
    #pragma unroll
    for (int u = 0; u < 3; u++) { int d = tid + u * 256; v[u] = x[d] + y[d]; sum += v[u]; }
    sum = blockReduceSum(sum, red);
    float m = sum / 768.f;
    float vs = 0.f;
    #pragma unroll
    for (int u = 0; u < 3; u++) { float d = v[u] - m; vs += d * d; }
    vs = blockReduceSum(vs, red);
    float inv = 1.f / sqrtf(vs / 768.f + 1e-5f);
    #pragma unroll
    for (int u = 0; u < 3; u++) { int d = tid + u * 256; x[d] = (v[u] - m) * inv * g[d] + be[d]; }
}

// ---------------- conv1d(k=3,pad=1)+BN+ReLU ----------------
template<int IC>
__global__ void conv3bn(const float* __restrict__ x, const float* __restrict__ w,
                        const float* __restrict__ cb, const float* __restrict__ g,
                        const float* __restrict__ bb, float* __restrict__ y) {
    const int TC = 8;
    __shared__ float xs[(TC + 2) * IC];
    int b = blockIdx.y, t0 = blockIdx.x * TC, tid = threadIdx.x;
    for (int l = tid; l < (TC + 2) * IC; l += 128) {
        int r = l / IC, c = l - r * IC;
        int t = t0 - 1 + r;
        xs[l] = (t >= 0 && t < NSEQ) ? x[((long long)(b * NSEQ + t)) * IC + c] : 0.f;
    }
    __syncthreads();
    int o = tid;
    float acc[TC];
    #pragma unroll
    for (int u = 0; u < TC; u++) acc[u] = cb[o];
    const float* wo = w + (long long)o * IC * 3;
    for (int i = 0; i < IC; i++) {
        float w0 = wo[i * 3 + 0], w1 = wo[i * 3 + 1], w2 = wo[i * 3 + 2];
        #pragma unroll
        for (int u = 0; u < TC; u++)
            acc[u] += xs[u * IC + i] * w0 + xs[(u + 1) * IC + i] * w1 + xs[(u + 2) * IC + i] * w2;
    }
    const float inv = 0.9999950000375f;
    float gg = g[o], bo = bb[o];
    #pragma unroll
    for (int u = 0; u < TC; u++) {
        float vv = acc[u] * inv * gg + bo;
        y[((long long)(b * NSEQ + t0 + u)) * HID + o] = fmaxf(vv, 0.f);
    }
}

// ---------------- sigma ----------------
__global__ void sigma_k(const float* __restrict__ h2, const float* __restrict__ ow,
                        const float* __restrict__ ob, float* __restrict__ sig) {
    int row = blockIdx.x;
    __shared__ float red[32];
    float v = h2[(long long)row * HID + threadIdx.x] * ow[threadIdx.x];
    v = blockReduceSum(v, red);
    if (threadIdx.x == 0) sig[row] = v + ob[0];
}

// ---------------- e, sq ----------------
__global__ void e_sq(const float* __restrict__ emb, const float* __restrict__ sig,
                     float* __restrict__ e, float* __restrict__ sq) {
    int row = blockIdx.x;
    const float* x = emb + (long long)row * DF;
    float* y = e + (long long)row * DF;
    float s = sig[row] + 1e-6f;
    __shared__ float red[32];
    int tid = threadIdx.x;
    float acc = 0.f;
    #pragma unroll
    for (int u = 0; u < 3; u++) {
        int d = tid + u * 256;
        float v = x[d] / s;
        y[d] = v;
        acc += v * v;
    }
    acc = blockReduceSum(acc, red);
    if (tid == 0) sq[row] = acc;
}

// ---------------- W = gaussian ----------------
__global__ void wexp(float* __restrict__ W, const float* __restrict__ sq) {
    long long idx = (long long)blockIdx.x * 256 + threadIdx.x;
    if (idx >= (long long)B * NSEQ * NSEQ) return;
    int c = (int)(idx & 511);
    int r = (int)((idx >> 9) & 511);
    int b = (int)(idx >> 18);
    float d2 = sq[b * NSEQ + r] + sq[b * NSEQ + c] - 2.f * W[idx];
    d2 = fmaxf(d2, 0.f);
    W[idx] = expf(-(d2 / 768.f) * 0.5f);
}

// ---------------- top-20 ----------------
__global__ void topk20(const float* __restrict__ W, int* __restrict__ ind) {
    int row = blockIdx.x;
    const float* x = W + (long long)row * NSEQ;
    int lane = threadIdx.x;
    float lv[16];
    #pragma unroll
    for (int j = 0; j < 16; j++) lv[j] = x[j * 32 + lane];
    for (int t = 0; t < TOPK; t++) {
        float bv = -2.f; int bi = 0;
        #pragma unroll
        for (int j = 0; j < 16; j++)
            if (lv[j] > bv) { bv = lv[j]; bi = j * 32 + lane; }
        #pragma unroll
        for (int off = 16; off; off >>= 1) {
            float ov = __shfl_down_sync(0xffffffffu, bv, off);
            int oi = __shfl_down_sync(0xffffffffu, bi, off);
            if (ov > bv || (ov == bv && oi < bi)) { bv = ov; bi = oi; }
        }
        bi = __shfl_sync(0xffffffffu, bi, 0);
        if (lane == 0) ind[row * TOPK + t] = bi;
        if (lane == (bi & 31)) {
            int js = bi >> 5;
            #pragma unroll
            for (int j = 0; j < 16; j++) if (j == js) lv[j] = -1.f;
        }
    }
}

// ---------------- mask scatter ----------------
__global__ void scat_mask(const int* __restrict__ ind, unsigned char* __restrict__ mk) {
    int row = blockIdx.x;
    int b = row >> 9, n = row & 511;
    if (threadIdx.x < TOPK) {
        int m = ind[row * TOPK + threadIdx.x];
        mk[((long long)(b * NSEQ + n)) * NSEQ + m] = 1;
        mk[((long long)(b * NSEQ + m)) * NSEQ + n] = 1;
    }
}

// ---------------- W*=mask, Dg ----------------
__global__ void maskW(float* __restrict__ W, const unsigned char* __restrict__ mk,
                      float* __restrict__ Dg) {
    int row = blockIdx.x;
    __shared__ float red[32];
    float sum = 0.f;
    for (int c = threadIdx.x; c < NSEQ; c += 256) {
        long long id = (long long)row * NSEQ + c;
        float w = mk[id] ? W[id] : 0.f;
        W[id] = w;
        sum += w;
    }
    sum = blockReduceSum(sum, red);
    if (threadIdx.x == 0) Dg[row] = sum;
}

// ---------------- A = (1+eps)I - alpha S ----------------
__global__ void buildA(const float* __restrict__ W, const float* __restrict__ Dg,
                       const float* __restrict__ alpha, float* __restrict__ A) {
    long long idx = (long long)blockIdx.x * 256 + threadIdx.x;
    if (idx >= (long long)B * NSEQ * NSEQ) return;
    int c = (int)(idx & 511);
    int r = (int)((idx >> 9) & 511);
    int b = (int)(idx >> 18);
    float al = alpha[0];
    float dr = sqrtf(1.f / (Dg[b * NSEQ + r] + 1e-6f));
    float dc = sqrtf(1.f / (Dg[b * NSEQ + c] + 1e-6f));
    float s = dr * W[idx] * dc;
    A[idx] = ((r == c) ? (1.f + 1e-6f) : 0.f) - al * s;
}

// ---------------- blocked Gauss-Jordan inversion ----------------
__global__ void gj_diag(float* __restrict__ Ag, int k) {
    extern __shared__ float s[];
    __shared__ float tcol[128];
    int b = blockIdx.x;
    float* Abase = Ag + (long long)b * NSEQ * NSEQ + (long long)(k * 128) * NSEQ + k * 128;
    int tid = threadIdx.x;
    for (int l = tid; l < 16384; l += 512) s[l] = Abase[(long long)(l >> 7) * NSEQ + (l & 127)];
    __syncthreads();
    for (int kk = 0; kk < 128; kk++) {
        float p = 1.0f / s[kk * 128 + kk];
        if (tid < 128) tcol[tid] = s[tid * 128 + kk];
        __syncthreads();
        if (tid < 128) s[kk * 128 + tid] = (tid == kk) ? p : s[kk * 128 + tid] * p;
        __syncthreads();
        int i = tid >> 2;
        int c0 = (tid & 3) * 32;
        if (i != kk) {
            float t = tcol[i];
            #pragma unroll 8
            for (int c = 0; c < 32; c++) {
                int j = c0 + c;
                if (j == kk) s[i * 128 + j] = -t * p;
                else         s[i * 128 + j] -= t * s[kk * 128 + j];
            }
        }
        __syncthreads();
    }
    for (int l = tid; l < 16384; l += 512) Abase[(long long)(l >> 7) * NSEQ + (l & 127)] = s[l];
}

__global__ void gj_panel(float* __restrict__ Ag, float* __restrict__ Tb, int k) {
    int b = blockIdx.y;
    int job = blockIdx.x;
    int jj = job % 3;
    int idx = jj + (jj >= k ? 1 : 0);
    float* Abase = Ag + (long long)b * NSEQ * NSEQ;
    if (job < 3) {
        const float* P = Abase + (long long)(k * 128) * NSEQ + k * 128;
        float* X = Abase + (long long)(k * 128) * NSEQ + idx * 128;
        __shared__ float As[16][132], Bs[16][132];
        int tid = threadIdx.x, tm = tid >> 4, tn = tid & 15;
        float acc[8][8] = {};
        for (int p0 = 0; p0 < 128; p0 += 16) {
            #pragma unroll
            for (int r = 0; r < 8; r++) { int l = tid + r * 256; int m = l >> 4, kk = l & 15;
                As[kk][m] = P[(long long)m * NSEQ + p0 + kk]; }
            #pragma unroll
            for (int r = 0; r < 8; r++) { int l = tid + r * 256; int kk = l >> 7, n = l & 127;
                Bs[kk][n] = X[(long long)(p0 + kk) * NSEQ + n]; }
            __syncthreads();
            #pragma unroll
            for (int kk = 0; kk < 16; kk++) {
                float a[8], bv[8];
                #pragma unroll
                for (int u = 0; u < 8; u++) { a[u] = As[kk][tm * 8 + u]; bv[u] = Bs[kk][tn * 8 + u]; }
                #pragma unroll
                for (int u = 0; u < 8; u++)
                    #pragma unroll
                    for (int v2 = 0; v2 < 8; v2++) acc[u][v2] += a[u] * bv[v2];
            }
            __syncthreads();
        }
        #pragma unroll
        for (int u = 0; u < 8; u++)
            #pragma unroll
            for (int v2 = 0; v2 < 8; v2++)
                X[(long long)(tm * 8 + u) * NSEQ + tn * 8 + v2] = acc[u][v2];
    } else {
        const float* S = Abase + (long long)(idx * 128) * NSEQ + k * 128;
        float* D = Tb + ((long long)b * 4 + idx) * 16384;
        for (int l = threadIdx.x; l < 16384; l += 256)
            D[l] = S[(long long)(l >> 7) * NSEQ + (l & 127)];
    }
}

__global__ void gj_update(float* __restrict__ Ag, const float* __restrict__ Tb, int k) {
    int b = blockIdx.y;
    int job = blockIdx.x;
    int ii = job >> 2;
    int i = ii + (ii >= k ? 1 : 0);
    int j = job & 3;
    float* Abase = Ag + (long long)b * NSEQ * NSEQ;
    const float* Tm = Tb + ((long long)b * 4 + i) * 16384;
    const float* Bm = Abase + (long long)(k * 128) * NSEQ + j * 128;
    float* Cm = Abase + (long long)(i * 128) * NSEQ + j * 128;
    __shared__ float As[16][132], Bs[16][132];
    int tid = threadIdx.x, tm = tid >> 4, tn = tid & 15;
    float acc[8][8] = {};
    for (int p0 = 0; p0 < 128; p0 += 16) {
        #pragma unroll
        for (int r = 0; r < 8; r++) { int l = tid + r * 256; int m = l >> 4, kk = l & 15;
            As[kk][m] = Tm[m * 128 + p0 + kk]; }
        #pragma unroll
        for (int r = 0; r < 8; r++) { int l = tid + r * 256; int kk = l >> 7, n = l & 127;
            Bs[kk][n] = Bm[(long long)(p0 + kk) * NSEQ + n]; }
        __syncthreads();
        #pragma unroll
        for (int kk = 0; kk < 16; kk++) {
            float a[8], bv[8];
            #pragma unroll
            for (int u = 0; u < 8; u++) { a[u] = As[kk][tm * 8 + u]; bv[u] = Bs[kk][tn * 8 + u]; }
            #pragma unroll
            for (int u = 0; u < 8; u++)
                #pragma unroll
                for (int v2 = 0; v2 < 8; v2++) acc[u][v2] += a[u] * bv[v2];
        }
        __syncthreads();
    }
    if (j != k) {
        #pragma unroll
        for (int u = 0; u < 8; u++)
            #pragma unroll
            for (int v2 = 0; v2 < 8; v2++) {
                long long id = (long long)(tm * 8 + u) * NSEQ + tn * 8 + v2;
                Cm[id] = Cm[id] - acc[u][v2];
            }
    } else {
        #pragma unroll
        for (int u = 0; u < 8; u++)
            #pragma unroll
            for (int v2 = 0; v2 < 8; v2++) {
                long long id = (long long)(tm * 8 + u) * NSEQ + tn * 8 + v2;
                Cm[id] = -acc[u][v2];
            }
    }
}

// ---------------- output scatter ----------------
__global__ void scat_out(const float* __restrict__ A, const int* __restrict__ labels,
                         float* __restrict__ out) {
    int m = blockIdx.x;
    int b = blockIdx.y;
    int v = labels[b * NSEQ + m];
    if (v < 0 || v >= VOCAB) return;
    const float* col = A + (long long)b * NSEQ * NSEQ + m;
    float* ob = out + (long long)b * NSEQ * VOCAB + v;
    for (int n = threadIdx.x; n < NSEQ; n += 256)
        atomicAdd(ob + (long long)n * VOCAB, col[(long long)n * NSEQ]);
}

// ==================================================================================
extern "C" void kernel_launch(void* const* d_in, const int* in_sizes, int n_in,
                              void* d_out, int out_size) {
    const float* ge     = (const float*)d_in[0];
    const float* ue     = (const float*)d_in[1];
    const float* hs     = (const float*)d_in[2];
    const int*   labels = (const int*)  d_in[3];
    const float* in_w   = (const float*)d_in[4];
    const float* in_b   = (const float*)d_in[5];
    const float* out_w  = (const float*)d_in[6];
    const float* out_b  = (const float*)d_in[7];
    const float* ln_g   = (const float*)d_in[8];
    const float* ln_b   = (const float*)d_in[9];
    const float* proj_w = (const float*)d_in[10];
    const float* proj_b = (const float*)d_in[11];
    const float* c1w    = (const float*)d_in[12];
    const float* c1b    = (const float*)d_in[13];
    const float* bn1g   = (const float*)d_in[14];
    const float* bn1b   = (const float*)d_in[15];
    const float* c2w    = (const float*)d_in[16];
    const float* c2b    = (const float*)d_in[17];
    const float* bn2g   = (const float*)d_in[18];
    const float* bn2b   = (const float*)d_in[19];
    const float* oww    = (const float*)d_in[20];
    const float* obb    = (const float*)d_in[21];
    const float* alpha  = (const float*)d_in[22];
    float* out = (float*)d_out;

    float *emb, *q, *k, *v, *sc, *o, *xp, *h1, *h2, *sig, *e, *sq, *W, *A, *T, *dg;
    unsigned char* mk; int* ind;
    cudaGetSymbolAddress((void**)&emb, g_emb);
    cudaGetSymbolAddress((void**)&q,   g_q);
    cudaGetSymbolAddress((void**)&k,   g_k);
    cudaGetSymbolAddress((void**)&v,   g_v);
    cudaGetSymbolAddress((void**)&sc,  g_sc);
    cudaGetSymbolAddress((void**)&o,   g_o);
    cudaGetSymbolAddress((void**)&xp,  g_xp);
    cudaGetSymbolAddress((void**)&h1,  g_h1);
    cudaGetSymbolAddress((void**)&h2,  g_h2);
    cudaGetSymbolAddress((void**)&sig, g_sig);
    cudaGetSymbolAddress((void**)&e,   g_e);
    cudaGetSymbolAddress((void**)&sq,  g_sq);
    cudaGetSymbolAddress((void**)&W,   g_W);
    cudaGetSymbolAddress((void**)&mk,  g_mk);
    cudaGetSymbolAddress((void**)&ind, g_ind);
    cudaGetSymbolAddress((void**)&dg,  g_dg);
    cudaGetSymbolAddress((void**)&A,   g_A);
    cudaGetSymbolAddress((void**)&T,   g_T);

    cudaFuncSetAttribute(gj_diag, cudaFuncAttributeMaxDynamicSharedMemorySize, 65536);

    // 1. embeddings + PE
    build_emb<<<(B*NSEQ*DF + 255) / 256, 256>>>(ge, ue, emb);

    // 2-4. QKV projections (C = X @ W^T + b)
    sgemm<true,128,8><<<dim3(6, 2, B), 256>>>(emb + IDX*DF, in_w, q, in_b,
        DF, DF, DF, DF, 1, (long long)NSEQ*DF, 0, 0, 0, (long long)IDX*DF, 0, 1.f);
    sgemm<true,128,8><<<dim3(6, 4, B), 256>>>(hs, in_w + DF*DF, k, in_b + DF,
        DF, DF, DF, DF, 1, (long long)NSEQ*DF, 0, 0, 0, (long long)NSEQ*DF, 0, 1.f);
    sgemm<true,128,8><<<dim3(6, 4, B), 256>>>(hs, in_w + 2*DF*DF, v, in_b + 2*DF,
        DF, DF, DF, DF, 1, (long long)NSEQ*DF, 0, 0, 0, (long long)NSEQ*DF, 0, 1.f);

    // 5. scores = QK^T / 8
    sgemm<true,128,8><<<dim3(4, 2, B*NH), 256>>>(q, k, sc, nullptr,
        HD, DF, DF, NSEQ, NH,
        (long long)IDX*DF, HD, (long long)NSEQ*DF, HD,
        (long long)NH*IDX*NSEQ, (long long)IDX*NSEQ, 0.125f);

    // 6. softmax
    softmax512<<<B*NH*IDX, 256>>>(sc);

    // 7. O = attn @ V  (B not transposed, N=64)
    sgemm<false,64,4><<<dim3(1, 2, B*NH), 256>>>(sc, v, o, nullptr,
        NSEQ, NSEQ, DF, DF, NH,
        (long long)NH*IDX*NSEQ, (long long)IDX*NSEQ, (long long)NSEQ*DF, HD,
        (long long)IDX*DF, HD, 1.f);

    // 8. out projection (dest q)
    sgemm<true,128,8><<<dim3(6, 2, B), 256>>>(o, out_w, q, out_b,
        DF, DF, DF, DF, 1, (long long)IDX*DF, 0, 0, 0, (long long)IDX*DF, 0, 1.f);

    // 9. residual + LN
    ln_res<<<B*IDX, 256>>>(emb, q, ln_g, ln_b);

    // 10. xp = emb @ proj_w^T + proj_b
    sgemm<true,128,8><<<dim3(2, 4, B), 256>>>(emb, proj_w, xp, proj_b,
        DF, DF, DF, PROJ, 1, (long long)NSEQ*DF, 0, 0, 0, (long long)NSEQ*PROJ, 0, 1.f);

    // 11-13. convs + sigma
    conv3bn<PROJ><<<dim3(64, B), 128>>>(xp, c1w, c1b, bn1g, bn1b, h1);
    conv3bn<HID ><<<dim3(64, B), 128>>>(h1, c2w, c2b, bn2g, bn2b, h2);
    sigma_k<<<B*NSEQ, 128>>>(h2, oww, obb, sig);

    // 14. e, sq
    e_sq<<<B*NSEQ, 256>>>(emb, sig, e, sq);

    // 15. Gram
    sgemm<true,128,8><<<dim3(4, 4, B), 256>>>(e, e, W, nullptr,
        DF, DF, DF, NSEQ, 1,
        (long long)NSEQ*DF, 0, (long long)NSEQ*DF, 0, (long long)NSEQ*NSEQ, 0, 1.f);

    // 16. W = exp(-d2/1536)
    wexp<<<(B*NSEQ*NSEQ + 255) / 256, 256>>>(W, sq);

    // 17-20. topk, mask, Dg
    topk20<<<B*NSEQ, 32>>>(W, ind);
    cudaMemsetAsync(mk, 0, (size_t)B*NSEQ*NSEQ);
    scat_mask<<<B*NSEQ, 32>>>(ind, mk);
    maskW<<<B*NSEQ, 256>>>(W, mk, dg);

    // 21. A
    buildA<<<(B*NSEQ*NSEQ + 255) / 256, 256>>>(W, dg, alpha, A);

    // 22-33. blocked GJ inverse
    for (int kb = 0; kb < 4; kb++) {
        gj_diag<<<B, 512, 65536>>>(A, kb);
        gj_panel<<<dim3(6, B), 256>>>(A, T, kb);
        gj_update<<<dim3(12, B), 256>>>(A, T, kb);
    }

    // 34-35. output scatter
    cudaMemsetAsync(out, 0, (size_t)out_size * sizeof(float));
    scat_out<<<dim3(NSEQ, B), 256>>>(A, labels, out);
}

// round 5
// speedup vs baseline: 1.0336x; 1.0005x over previous
#include <cuda_runtime.h>
#include <math.h>

#define B 8
#define NSEQ 512
#define IDX 256
#define HCTX 512
#define DF 768
#define PROJ 256
#define HID 128
#define NH 12
#define HD 64
#define VOCAB 16384
#define TOPK 20

// ---------------- scratch ----------------
__device__ float g_emb[B*NSEQ*DF];
__device__ float g_q  [B*IDX*DF];
__device__ float g_k  [B*NSEQ*DF];
__device__ float g_v  [B*NSEQ*DF];
__device__ float g_sc [B*NH*IDX*NSEQ];
__device__ float g_o  [B*IDX*DF];
__device__ float g_xp [B*NSEQ*PROJ];
__device__ float g_h1 [B*NSEQ*HID];
__device__ float g_h2 [B*NSEQ*HID];
__device__ float g_sig[B*NSEQ];
__device__ float g_e  [B*NSEQ*DF];
__device__ float g_sq [B*NSEQ];
__device__ float g_W  [B*NSEQ*NSEQ];
__device__ unsigned char g_mk[B*NSEQ*NSEQ];
__device__ int   g_ind[B*NSEQ*TOPK];
__device__ float g_dg [B*NSEQ];
__device__ float g_A  [B*NSEQ*NSEQ];
__device__ float g_T  [B*4*128*128];

// ---------------- reductions ----------------
__device__ __forceinline__ float blockReduceSum(float val, float* red) {
    int lane = threadIdx.x & 31, wid = threadIdx.x >> 5;
    #pragma unroll
    for (int off = 16; off; off >>= 1) val += __shfl_down_sync(0xffffffffu, val, off);
    if (lane == 0) red[wid] = val;
    __syncthreads();
    int nw = blockDim.x >> 5;
    val = (threadIdx.x < nw) ? red[threadIdx.x] : 0.f;
    if (wid == 0) {
        #pragma unroll
        for (int off = 16; off; off >>= 1) val += __shfl_down_sync(0xffffffffu, val, off);
        if (lane == 0) red[0] = val;
    }
    __syncthreads();
    float r = red[0];
    __syncthreads();
    return r;
}

__device__ __forceinline__ float blockReduceMax(float val, float* red) {
    int lane = threadIdx.x & 31, wid = threadIdx.x >> 5;
    #pragma unroll
    for (int off = 16; off; off >>= 1) val = fmaxf(val, __shfl_down_sync(0xffffffffu, val, off));
    if (lane == 0) red[wid] = val;
    __syncthreads();
    int nw = blockDim.x >> 5;
    val = (threadIdx.x < nw) ? red[threadIdx.x] : -3.4e38f;
    if (wid == 0) {
        #pragma unroll
        for (int off = 16; off; off >>= 1) val = fmaxf(val, __shfl_down_sync(0xffffffffu, val, off));
        if (lane == 0) red[0] = val;
    }
    __syncthreads();
    float r = red[0];
    __syncthreads();
    return r;
}

// ---------------- emb = concat(ge,ue) + PE ----------------
__global__ void build_emb(const float* __restrict__ ge, const float* __restrict__ ue,
                          float* __restrict__ emb) {
    long long idx = (long long)blockIdx.x * 256 + threadIdx.x;
    if (idx >= (long long)B*NSEQ*DF) return;
    int d = (int)(idx % DF);
    long long bn = idx / DF;
    int n = (int)(bn % NSEQ);
    int b = (int)(bn / NSEQ);
    float src = (n < IDX) ? ge[((long long)b*IDX + n)*DF + d]
                          : ue[((long long)b*IDX + (n - IDX))*DF + d];
    int i = d >> 1;
    float coef = (float)(-9.210340371976184 / 768.0);
    float div = expf((float)(2 * i) * coef);
    float ang = (float)n * div;
    float pe = (d & 1) ? cosf(ang) : sinf(ang);
    emb[idx] = src + pe;
}

// ==================================================================================
// Fast SGEMM: BM=128, BK=8, TM=8; BN/TN template (128/8 or 64/4); 256 threads.
// No bounds checks: requires M%128==0? No — M%128 handled by exact grid (all M are
// 256/512), N%BN==0, K%8==0, all pointers/ld 16B-aligned. Double-buffered smem.
// TB=true: B is [N,K] row-major (C = A@B^T). TB=false: B is [K,N].
// ==================================================================================
template<bool TB, int BN, int TN>
__global__ void __launch_bounds__(256) sgemm(
        const float* __restrict__ A, const float* __restrict__ Bp,
        float* __restrict__ C, const float* __restrict__ bias,
        int K, int lda, int ldb, int ldc,
        int ZH, long long Ab, long long Ah, long long Bb, long long Bh,
        long long Cb, long long Ch, float scale) {
    const int BM = 128, BK = 8, TM = 8;
    __shared__ float As[2][BK][BM + 4];
    __shared__ float Bs[2][BK][BN + 4];

    int z = blockIdx.z;
    int zb = z / ZH, zh = z - zb * ZH;
    A  += zb * Ab + zh * Ah;
    Bp += zb * Bb + zh * Bh;
    C  += zb * Cb + zh * Ch;
    int m0 = blockIdx.y * BM, n0 = blockIdx.x * BN;
    int tid = threadIdx.x;

    // A tile loader: 128 rows x 8 k -> 256 float4
    int a_row = tid >> 1;
    int a_kq  = (tid & 1) * 4;
    const float* Aptr = A + (long long)(m0 + a_row) * lda + a_kq;

    // B tile loader indices
    int b_row, b_kq, b_k, b_nq;
    const float* Bptr;
    if (TB) {
        if (BN == 128) { b_row = tid >> 1; b_kq = (tid & 1) * 4; }
        else           { b_row = tid >> 1; b_kq = (tid & 1) * 4; } // tid<128 active
        Bptr = Bp + (long long)(n0 + b_row) * ldb + b_kq;
        b_k = 0; b_nq = 0;
    } else {
        if (BN == 128) { b_k = tid >> 5; b_nq = (tid & 31) * 4; }
        else           { b_k = tid >> 4; b_nq = (tid & 15) * 4; } // tid<128 active
        Bptr = Bp + (long long)b_k * ldb + n0 + b_nq;
        b_row = 0; b_kq = 0;
    }
    const bool b_act = (BN == 128) || (tid < 128);

    int tn = tid & 15;          // 16 cols of threads
    int tm = tid >> 4;          // 16 rows of threads
    float acc[TM][TN];
    #pragma unroll
    for (int u = 0; u < TM; u++)
        #pragma unroll
        for (int v = 0; v < TN; v++) acc[u][v] = 0.f;

    int nt = K / BK;

    // --- load tile 0 ---
    {
        float4 ra = *(const float4*)Aptr;
        As[0][a_kq + 0][a_row] = ra.x;
        As[0][a_kq + 1][a_row] = ra.y;
        As[0][a_kq + 2][a_row] = ra.z;
        As[0][a_kq + 3][a_row] = ra.w;
        if (b_act) {
            float4 rb = *(const float4*)Bptr;
            if (TB) {
                Bs[0][b_kq + 0][b_row] = rb.x;
                Bs[0][b_kq + 1][b_row] = rb.y;
                Bs[0][b_kq + 2][b_row] = rb.z;
                Bs[0][b_kq + 3][b_row] = rb.w;
            } else {
                *(float4*)&Bs[0][b_k][b_nq] = rb;
            }
        }
    }
    __syncthreads();

    for (int t = 0; t < nt; t++) {
        int cur = t & 1;
        float4 ra, rb;
        bool pre = (t + 1 < nt);
        if (pre) {
            ra = *(const float4*)(Aptr + (long long)(t + 1) * BK);
            if (b_act) {
                if (TB) rb = *(const float4*)(Bptr + (long long)(t + 1) * BK);
                else    rb = *(const float4*)(Bptr + (long long)(t + 1) * BK * ldb);
            }
        }
        #pragma unroll
        for (int kk = 0; kk < BK; kk++) {
            float a[TM], bb[TN];
            #pragma unroll
            for (int u = 0; u < TM; u++) a[u] = As[cur][kk][tm * TM + u];
            #pragma unroll
            for (int v = 0; v < TN; v++) bb[v] = Bs[cur][kk][tn * TN + v];
            #pragma unroll
            for (int u = 0; u < TM; u++)
                #pragma unroll
                for (int v = 0; v < TN; v++) acc[u][v] += a[u] * bb[v];
        }
        if (pre) {
            int nxt = cur ^ 1;
            As[nxt][a_kq + 0][a_row] = ra.x;
            As[nxt][a_kq + 1][a_row] = ra.y;
            As[nxt][a_kq + 2][a_row] = ra.z;
            As[nxt][a_kq + 3][a_row] = ra.w;
            if (b_act) {
                if (TB) {
                    Bs[nxt][b_kq + 0][b_row] = rb.x;
                    Bs[nxt][b_kq + 1][b_row] = rb.y;
                    Bs[nxt][b_kq + 2][b_row] = rb.z;
                    Bs[nxt][b_kq + 3][b_row] = rb.w;
                } else {
                    *(float4*)&Bs[nxt][b_k][b_nq] = rb;
                }
            }
            __syncthreads();
        }
    }

    // --- epilogue ---
    #pragma unroll
    for (int u = 0; u < TM; u++) {
        int m = m0 + tm * TM + u;
        float* Crow = C + (long long)m * ldc + n0 + tn * TN;
        #pragma unroll
        for (int v = 0; v < TN; v += 4) {
            float4 o;
            o.x = acc[u][v + 0] * scale;
            o.y = acc[u][v + 1] * scale;
            o.z = acc[u][v + 2] * scale;
            o.w = acc[u][v + 3] * scale;
            if (bias) {
                const float* bp = bias + n0 + tn * TN + v;
                o.x += bp[0]; o.y += bp[1]; o.z += bp[2]; o.w += bp[3];
            }
            *(float4*)(Crow + v) = o;
        }
    }
}

// ---------------- softmax over 512 (in place) ----------------
__global__ void softmax512(float* __restrict__ sc) {
    float* x = sc + (long long)blockIdx.x * NSEQ;
    __shared__ float red[32];
    int tid = threadIdx.x;
    float v0 = x[tid], v1 = x[tid + 256];
    float mx = blockReduceMax(fmaxf(v0, v1), red);
    float e0 = expf(v0 - mx), e1 = expf(v1 - mx);
    float s = blockReduceSum(e0 + e1, red);
    float inv = 1.f / s;
    x[tid] = e0 * inv;
    x[tid + 256] = e1 * inv;
}

// ---------------- u = LN(u + mha_out) ----------------
__global__ void ln_res(float* __restrict__ emb, const float* __restrict__ mo,
                       const float* __restrict__ g, const float* __restrict__ be) {
    int row = blockIdx.x;
    int b = row >> 8, i = row & 255;
    float* x = emb + ((long long)(b * NSEQ + IDX + i)) * DF;
    const float* y = mo + ((long long)(b * IDX + i)) * DF;
    __shared__ float red[32];
    int tid = threadIdx.x;
    float v[3]; float sum = 0.f;
    #pragma unroll
    for (int u = 0; u < 3; u++) { int d = tid + u * 256; v[u] = x[d] + y[d]; sum += v[u]; }
    sum = blockReduceSum(sum, red);
    float m = sum / 768.f;
    float vs = 0.f;
    #pragma unroll
    for (int u = 0; u < 3; u++) { float d = v[u] - m; vs += d * d; }
    vs = blockReduceSum(vs, red);
    float inv = 1.f / sqrtf(vs / 768.f + 1e-5f);
    #pragma unroll
    for (int u = 0; u < 3; u++) { int d = tid + u * 256; x[d] = (v[u] - m) * inv * g[d] + be[d]; }
}

// ---------------- conv1d(k=3,pad=1)+BN+ReLU ----------------
template<int IC>
__global__ void conv3bn(const float* __restrict__ x, const float* __restrict__ w,
                        const float* __restrict__ cb, const float* __restrict__ g,
                        const float* __restrict__ bb, float* __restrict__ y) {
    const int TC = 8;
    __shared__ float xs[(TC + 2) * IC];
    int b = blockIdx.y, t0 = blockIdx.x * TC, tid = threadIdx.x;
    for (int l = tid; l < (TC + 2) * IC; l += 128) {
        int r = l / IC, c = l - r * IC;
        int t = t0 - 1 + r;
        xs[l] = (t >= 0 && t < NSEQ) ? x[((long long)(b * NSEQ + t)) * IC + c] : 0.f;
    }
    __syncthreads();
    int o = tid;
    float acc[TC];
    #pragma unroll
    for (int u = 0; u < TC; u++) acc[u] = cb[o];
    const float* wo = w + (long long)o * IC * 3;
    for (int i = 0; i < IC; i++) {
        float w0 = wo[i * 3 + 0], w1 = wo[i * 3 + 1], w2 = wo[i * 3 + 2];
        #pragma unroll
        for (int u = 0; u < TC; u++)
            acc[u] += xs[u * IC + i] * w0 + xs[(u + 1) * IC + i] * w1 + xs[(u + 2) * IC + i] * w2;
    }
    const float inv = 0.9999950000375f;
    float gg = g[o], bo = bb[o];
    #pragma unroll
    for (int u = 0; u < TC; u++) {
        float vv = acc[u] * inv * gg + bo;
        y[((long long)(b * NSEQ + t0 + u)) * HID + o] = fmaxf(vv, 0.f);
    }
}

// ---------------- sigma ----------------
__global__ void sigma_k(const float* __restrict__ h2, const float* __restrict__ ow,
                        const float* __restrict__ ob, float* __restrict__ sig) {
    int row = blockIdx.x;
    __shared__ float red[32];
    float v = h2[(long long)row * HID + threadIdx.x] * ow[threadIdx.x];
    v = blockReduceSum(v, red);
    if (threadIdx.x == 0) sig[row] = v + ob[0];
}

// ---------------- e, sq ----------------
__global__ void e_sq(const float* __restrict__ emb, const float* __restrict__ sig,
                     float* __restrict__ e, float* __restrict__ sq) {
    int row = blockIdx.x;
    const float* x = emb + (long long)row * DF;
    float* y = e + (long long)row * DF;
    float s = sig[row] + 1e-6f;
    __shared__ float red[32];
    int tid = threadIdx.x;
    float acc = 0.f;
    #pragma unroll
    for (int u = 0; u < 3; u++) {
        int d = tid + u * 256;
        float v = x[d] / s;
        y[d] = v;
        acc += v * v;
    }
    acc = blockReduceSum(acc, red);
    if (tid == 0) sq[row] = acc;
}

// ---------------- W = gaussian ----------------
__global__ void wexp(float* __restrict__ W, const float* __restrict__ sq) {
    long long idx = (long long)blockIdx.x * 256 + threadIdx.x;
    if (idx >= (long long)B * NSEQ * NSEQ) return;
    int c = (int)(idx & 511);
    int r = (int)((idx >> 9) & 511);
    int b = (int)(idx >> 18);
    float d2 = sq[b * NSEQ + r] + sq[b * NSEQ + c] - 2.f * W[idx];
    d2 = fmaxf(d2, 0.f);
    W[idx] = expf(-(d2 / 768.f) * 0.5f);
}

// ---------------- top-20 ----------------
__global__ void topk20(const float* __restrict__ W, int* __restrict__ ind) {
    int row = blockIdx.x;
    const float* x = W + (long long)row * NSEQ;
    int lane = threadIdx.x;
    float lv[16];
    #pragma unroll
    for (int j = 0; j < 16; j++) lv[j] = x[j * 32 + lane];
    for (int t = 0; t < TOPK; t++) {
        float bv = -2.f; int bi = 0;
        #pragma unroll
        for (int j = 0; j < 16; j++)
            if (lv[j] > bv) { bv = lv[j]; bi = j * 32 + lane; }
        #pragma unroll
        for (int off = 16; off; off >>= 1) {
            float ov = __shfl_down_sync(0xffffffffu, bv, off);
            int oi = __shfl_down_sync(0xffffffffu, bi, off);
            if (ov > bv || (ov == bv && oi < bi)) { bv = ov; bi = oi; }
        }
        bi = __shfl_sync(0xffffffffu, bi, 0);
        if (lane == 0) ind[row * TOPK + t] = bi;
        if (lane == (bi & 31)) {
            int js = bi >> 5;
            #pragma unroll
            for (int j = 0; j < 16; j++) if (j == js) lv[j] = -1.f;
        }
    }
}

// ---------------- mask scatter ----------------
__global__ void scat_mask(const int* __restrict__ ind, unsigned char* __restrict__ mk) {
    int row = blockIdx.x;
    int b = row >> 9, n = row & 511;
    if (threadIdx.x < TOPK) {
        int m = ind[row * TOPK + threadIdx.x];
        mk[((long long)(b * NSEQ + n)) * NSEQ + m] = 1;
        mk[((long long)(b * NSEQ + m)) * NSEQ + n] = 1;
    }
}

// ---------------- W*=mask, Dg ----------------
__global__ void maskW(float* __restrict__ W, const unsigned char* __restrict__ mk,
                      float* __restrict__ Dg) {
    int row = blockIdx.x;
    __shared__ float red[32];
    float sum = 0.f;
    for (int c = threadIdx.x; c < NSEQ; c += 256) {
        long long id = (long long)row * NSEQ + c;
        float w = mk[id] ? W[id] : 0.f;
        W[id] = w;
        sum += w;
    }
    sum = blockReduceSum(sum, red);
    if (threadIdx.x == 0) Dg[row] = sum;
}

// ---------------- A = (1+eps)I - alpha S ----------------
__global__ void buildA(const float* __restrict__ W, const float* __restrict__ Dg,
                       const float* __restrict__ alpha, float* __restrict__ A) {
    long long idx = (long long)blockIdx.x * 256 + threadIdx.x;
    if (idx >= (long long)B * NSEQ * NSEQ) return;
    int c = (int)(idx & 511);
    int r = (int)((idx >> 9) & 511);
    int b = (int)(idx >> 18);
    float al = alpha[0];
    float dr = sqrtf(1.f / (Dg[b * NSEQ + r] + 1e-6f));
    float dc = sqrtf(1.f / (Dg[b * NSEQ + c] + 1e-6f));
    float s = dr * W[idx] * dc;
    A[idx] = ((r == c) ? (1.f + 1e-6f) : 0.f) - al * s;
}

// ---------------- blocked Gauss-Jordan inversion ----------------
__global__ void gj_diag(float* __restrict__ Ag, int k) {
    extern __shared__ float s[];
    __shared__ float tcol[128];
    int b = blockIdx.x;
    float* Abase = Ag + (long long)b * NSEQ * NSEQ + (long long)(k * 128) * NSEQ + k * 128;
    int tid = threadIdx.x;
    for (int l = tid; l < 16384; l += 512) s[l] = Abase[(long long)(l >> 7) * NSEQ + (l & 127)];
    __syncthreads();
    for (int kk = 0; kk < 128; kk++) {
        float p = 1.0f / s[kk * 128 + kk];
        if (tid < 128) tcol[tid] = s[tid * 128 + kk];
        __syncthreads();
        if (tid < 128) s[kk * 128 + tid] = (tid == kk) ? p : s[kk * 128 + tid] * p;
        __syncthreads();
        int i = tid >> 2;
        int c0 = (tid & 3) * 32;
        if (i != kk) {
            float t = tcol[i];
            #pragma unroll 8
            for (int c = 0; c < 32; c++) {
                int j = c0 + c;
                if (j == kk) s[i * 128 + j] = -t * p;
                else         s[i * 128 + j] -= t * s[kk * 128 + j];
            }
        }
        __syncthreads();
    }
    for (int l = tid; l < 16384; l += 512) Abase[(long long)(l >> 7) * NSEQ + (l & 127)] = s[l];
}

__global__ void gj_panel(float* __restrict__ Ag, float* __restrict__ Tb, int k) {
    int b = blockIdx.y;
    int job = blockIdx.x;
    int jj = job % 3;
    int idx = jj + (jj >= k ? 1 : 0);
    float* Abase = Ag + (long long)b * NSEQ * NSEQ;
    if (job < 3) {
        const float* P = Abase + (long long)(k * 128) * NSEQ + k * 128;
        float* X = Abase + (long long)(k * 128) * NSEQ + idx * 128;
        __shared__ float As[16][132], Bs[16][132];
        int tid = threadIdx.x, tm = tid >> 4, tn = tid & 15;
        float acc[8][8] = {};
        for (int p0 = 0; p0 < 128; p0 += 16) {
            #pragma unroll
            for (int r = 0; r < 8; r++) { int l = tid + r * 256; int m = l >> 4, kk = l & 15;
                As[kk][m] = P[(long long)m * NSEQ + p0 + kk]; }
            #pragma unroll
            for (int r = 0; r < 8; r++) { int l = tid + r * 256; int kk = l >> 7, n = l & 127;
                Bs[kk][n] = X[(long long)(p0 + kk) * NSEQ + n]; }
            __syncthreads();
            #pragma unroll
            for (int kk = 0; kk < 16; kk++) {
                float a[8], bv[8];
                #pragma unroll
                for (int u = 0; u < 8; u++) { a[u] = As[kk][tm * 8 + u]; bv[u] = Bs[kk][tn * 8 + u]; }
                #pragma unroll
                for (int u = 0; u < 8; u++)
                    #pragma unroll
                    for (int v2 = 0; v2 < 8; v2++) acc[u][v2] += a[u] * bv[v2];
            }
            __syncthreads();
        }
        #pragma unroll
        for (int u = 0; u < 8; u++)
            #pragma unroll
            for (int v2 = 0; v2 < 8; v2++)
                X[(long long)(tm * 8 + u) * NSEQ + tn * 8 + v2] = acc[u][v2];
    } else {
        const float* S = Abase + (long long)(idx * 128) * NSEQ + k * 128;
        float* D = Tb + ((long long)b * 4 + idx) * 16384;
        for (int l = threadIdx.x; l < 16384; l += 256)
            D[l] = S[(long long)(l >> 7) * NSEQ + (l & 127)];
    }
}

__global__ void gj_update(float* __restrict__ Ag, const float* __restrict__ Tb, int k) {
    int b = blockIdx.y;
    int job = blockIdx.x;
    int ii = job >> 2;
    int i = ii + (ii >= k ? 1 : 0);
    int j = job & 3;
    float* Abase = Ag + (long long)b * NSEQ * NSEQ;
    const float* Tm = Tb + ((long long)b * 4 + i) * 16384;
    const float* Bm = Abase + (long long)(k * 128) * NSEQ + j * 128;
    float* Cm = Abase + (long long)(i * 128) * NSEQ + j * 128;
    __shared__ float As[16][132], Bs[16][132];
    int tid = threadIdx.x, tm = tid >> 4, tn = tid & 15;
    float acc[8][8] = {};
    for (int p0 = 0; p0 < 128; p0 += 16) {
        #pragma unroll
        for (int r = 0; r < 8; r++) { int l = tid + r * 256; int m = l >> 4, kk = l & 15;
            As[kk][m] = Tm[m * 128 + p0 + kk]; }
        #pragma unroll
        for (int r = 0; r < 8; r++) { int l = tid + r * 256; int kk = l >> 7, n = l & 127;
            Bs[kk][n] = Bm[(long long)(p0 + kk) * NSEQ + n]; }
        __syncthreads();
        #pragma unroll
        for (int kk = 0; kk < 16; kk++) {
            float a[8], bv[8];
            #pragma unroll
            for (int u = 0; u < 8; u++) { a[u] = As[kk][tm * 8 + u]; bv[u] = Bs[kk][tn * 8 + u]; }
            #pragma unroll
            for (int u = 0; u < 8; u++)
                #pragma unroll
                for (int v2 = 0; v2 < 8; v2++) acc[u][v2] += a[u] * bv[v2];
        }
        __syncthreads();
    }
    if (j != k) {
        #pragma unroll
        for (int u = 0; u < 8; u++)
            #pragma unroll
            for (int v2 = 0; v2 < 8; v2++) {
                long long id = (long long)(tm * 8 + u) * NSEQ + tn * 8 + v2;
                Cm[id] = Cm[id] - acc[u][v2];
            }
    } else {
        #pragma unroll
        for (int u = 0; u < 8; u++)
            #pragma unroll
            for (int v2 = 0; v2 < 8; v2++) {
                long long id = (long long)(tm * 8 + u) * NSEQ + tn * 8 + v2;
                Cm[id] = -acc[u][v2];
            }
    }
}

// ---------------- output scatter ----------------
__global__ void scat_out(const float* __restrict__ A, const int* __restrict__ labels,
                         float* __restrict__ out) {
    int m = blockIdx.x;
    int b = blockIdx.y;
    int v = labels[b * NSEQ + m];
    if (v < 0 || v >= VOCAB) return;
    const float* col = A + (long long)b * NSEQ * NSEQ + m;
    float* ob = out + (long long)b * NSEQ * VOCAB + v;
    for (int n = threadIdx.x; n < NSEQ; n += 256)
        atomicAdd(ob + (long long)n * VOCAB, col[(long long)n * NSEQ]);
}

// ==================================================================================
extern "C" void kernel_launch(void* const* d_in, const int* in_sizes, int n_in,
                              void* d_out, int out_size) {
    const float* ge     = (const float*)d_in[0];
    const float* ue     = (const float*)d_in[1];
    const float* hs     = (const float*)d_in[2];
    const int*   labels = (const int*)  d_in[3];
    const float* in_w   = (const float*)d_in[4];
    const float* in_b   = (const float*)d_in[5];
    const float* out_w  = (const float*)d_in[6];
    const float* out_b  = (const float*)d_in[7];
    const float* ln_g   = (const float*)d_in[8];
    const float* ln_b   = (const float*)d_in[9];
    const float* proj_w = (const float*)d_in[10];
    const float* proj_b = (const float*)d_in[11];
    const float* c1w    = (const float*)d_in[12];
    const float* c1b    = (const float*)d_in[13];
    const float* bn1g   = (const float*)d_in[14];
    const float* bn1b   = (const float*)d_in[15];
    const float* c2w    = (const float*)d_in[16];
    const float* c2b    = (const float*)d_in[17];
    const float* bn2g   = (const float*)d_in[18];
    const float* bn2b   = (const float*)d_in[19];
    const float* oww    = (const float*)d_in[20];
    const float* obb    = (const float*)d_in[21];
    const float* alpha  = (const float*)d_in[22];
    float* out = (float*)d_out;

    float *emb, *q, *k, *v, *sc, *o, *xp, *h1, *h2, *sig, *e, *sq, *W, *A, *T, *dg;
    unsigned char* mk; int* ind;
    cudaGetSymbolAddress((void**)&emb, g_emb);
    cudaGetSymbolAddress((void**)&q,   g_q);
    cudaGetSymbolAddress((void**)&k,   g_k);
    cudaGetSymbolAddress((void**)&v,   g_v);
    cudaGetSymbolAddress((void**)&sc,  g_sc);
    cudaGetSymbolAddress((void**)&o,   g_o);
    cudaGetSymbolAddress((void**)&xp,  g_xp);
    cudaGetSymbolAddress((void**)&h1,  g_h1);
    cudaGetSymbolAddress((void**)&h2,  g_h2);
    cudaGetSymbolAddress((void**)&sig, g_sig);
    cudaGetSymbolAddress((void**)&e,   g_e);
    cudaGetSymbolAddress((void**)&sq,  g_sq);
    cudaGetSymbolAddress((void**)&W,   g_W);
    cudaGetSymbolAddress((void**)&mk,  g_mk);
    cudaGetSymbolAddress((void**)&ind, g_ind);
    cudaGetSymbolAddress((void**)&dg,  g_dg);
    cudaGetSymbolAddress((void**)&A,   g_A);
    cudaGetSymbolAddress((void**)&T,   g_T);

    cudaFuncSetAttribute(gj_diag, cudaFuncAttributeMaxDynamicSharedMemorySize, 65536);

    // 1. embeddings + PE
    build_emb<<<(B*NSEQ*DF + 255) / 256, 256>>>(ge, ue, emb);

    // 2-4. QKV projections (C = X @ W^T + b)
    sgemm<true,128,8><<<dim3(6, 2, B), 256>>>(emb + IDX*DF, in_w, q, in_b,
        DF, DF, DF, DF, 1, (long long)NSEQ*DF, 0, 0, 0, (long long)IDX*DF, 0, 1.f);
    sgemm<true,128,8><<<dim3(6, 4, B), 256>>>(hs, in_w + DF*DF, k, in_b + DF,
        DF, DF, DF, DF, 1, (long long)NSEQ*DF, 0, 0, 0, (long long)NSEQ*DF, 0, 1.f);
    sgemm<true,128,8><<<dim3(6, 4, B), 256>>>(hs, in_w + 2*DF*DF, v, in_b + 2*DF,
        DF, DF, DF, DF, 1, (long long)NSEQ*DF, 0, 0, 0, (long long)NSEQ*DF, 0, 1.f);

    // 5. scores = QK^T / 8
    sgemm<true,128,8><<<dim3(4, 2, B*NH), 256>>>(q, k, sc, nullptr,
        HD, DF, DF, NSEQ, NH,
        (long long)IDX*DF, HD, (long long)NSEQ*DF, HD,
        (long long)NH*IDX*NSEQ, (long long)IDX*NSEQ, 0.125f);

    // 6. softmax
    softmax512<<<B*NH*IDX, 256>>>(sc);

    // 7. O = attn @ V  (B not transposed, N=64)
    sgemm<false,64,4><<<dim3(1, 2, B*NH), 256>>>(sc, v, o, nullptr,
        NSEQ, NSEQ, DF, DF, NH,
        (long long)NH*IDX*NSEQ, (long long)IDX*NSEQ, (long long)NSEQ*DF, HD,
        (long long)IDX*DF, HD, 1.f);

    // 8. out projection (dest q)
    sgemm<true,128,8><<<dim3(6, 2, B), 256>>>(o, out_w, q, out_b,
        DF, DF, DF, DF, 1, (long long)IDX*DF, 0, 0, 0, (long long)IDX*DF, 0, 1.f);

    // 9. residual + LN
    ln_res<<<B*IDX, 256>>>(emb, q, ln_g, ln_b);

    // 10. xp = emb @ proj_w^T + proj_b
    sgemm<true,128,8><<<dim3(2, 4, B), 256>>>(emb, proj_w, xp, proj_b,
        DF, DF, DF, PROJ, 1, (long long)NSEQ*DF, 0, 0, 0, (long long)NSEQ*PROJ, 0, 1.f);

    // 11-13. convs + sigma
    conv3bn<PROJ><<<dim3(64, B), 128>>>(xp, c1w, c1b, bn1g, bn1b, h1);
    conv3bn<HID ><<<dim3(64, B), 128>>>(h1, c2w, c2b, bn2g, bn2b, h2);
    sigma_k<<<B*NSEQ, 128>>>(h2, oww, obb, sig);

    // 14. e, sq
    e_sq<<<B*NSEQ, 256>>>(emb, sig, e, sq);

    // 15. Gram
    sgemm<true,128,8><<<dim3(4, 4, B), 256>>>(e, e, W, nullptr,
        DF, DF, DF, NSEQ, 1,
        (long long)NSEQ*DF, 0, (long long)NSEQ*DF, 0, (long long)NSEQ*NSEQ, 0, 1.f);

    // 16. W = exp(-d2/1536)
    wexp<<<(B*NSEQ*NSEQ + 255) / 256, 256>>>(W, sq);

    // 17-20. topk, mask, Dg
    topk20<<<B*NSEQ, 32>>>(W, ind);
    cudaMemsetAsync(mk, 0, (size_t)B*NSEQ*NSEQ);
    scat_mask<<<B*NSEQ, 32>>>(ind, mk);
    maskW<<<B*NSEQ, 256>>>(W, mk, dg);

    // 21. A
    buildA<<<(B*NSEQ*NSEQ + 255) / 256, 256>>>(W, dg, alpha, A);

    // 22-33. blocked GJ inverse
    for (int kb = 0; kb < 4; kb++) {
        gj_diag<<<B, 512, 65536>>>(A, kb);
        gj_panel<<<dim3(6, B), 256>>>(A, T, kb);
        gj_update<<<dim3(12, B), 256>>>(A, T, kb);
    }

    // 34-35. output scatter
    cudaMemsetAsync(out, 0, (size_t)out_size * sizeof(float));
    scat_out<<<dim3(NSEQ, B), 256>>>(A, labels, out);
}